// round 14
// baseline (speedup 1.0000x reference)
#include <cuda_runtime.h>
#include <cuda_bf16.h>
#include <math.h>
#include <stdint.h>

// ---------------- problem constants ----------------
#define LNUM 2
#define BB   4
#define TT   1000
#define CC   768
#define HH   12
#define DKK  64
#define WHALF 50         // band half-width (WIN//2)
#define NR   101         // relative positions actually reachable: -50..50
#define BT   (BB*TT)     // 4000 rows
#define WSZ  (LNUM*CC*CC)

// ---------------- device scratch (no allocs allowed) ----------------
__device__ float g_h[BT*CC];
__device__ __nv_bfloat16 g_ybf[BT*CC];        // LN output (GEMM A operand)
__device__ __nv_bfloat16 g_obf[BT*CC];        // attn out / gelu out (GEMM A operand)
__device__ __nv_bfloat16 g_qb[BT*CC];
__device__ __nv_bfloat16 g_kb[BT*CC];
__device__ __nv_bfloat16 g_vb[BT*CC];
__device__ __nv_bfloat16 g_pcb[NR*CC];        // pe @ Wp[l], bf16
__device__ __nv_bfloat16 g_pebf[NR*CC];       // positional table, bf16
__device__ __nv_bfloat16 g_wbf[7*WSZ];        // bf16 weights: Wq,Wk,Wv,Wo,Wp,W1,W2

// ---------------- small kernels ----------------
__global__ void init_h_kernel(const float* __restrict__ x) {
    int i = blockIdx.x * blockDim.x + threadIdx.x;
    if (i < BT*CC) g_h[i] = x[i] * 27.712812921102035f;  // sqrt(768)
}

// one kernel converts all 7 weight tensors fp32 -> bf16 (float4 vectorized)
__global__ void f2b_all_kernel(const float* __restrict__ s0, const float* __restrict__ s1,
                               const float* __restrict__ s2, const float* __restrict__ s3,
                               const float* __restrict__ s4, const float* __restrict__ s5,
                               const float* __restrict__ s6) {
    const int per = WSZ / 4;                       // float4 chunks per tensor
    int i4 = blockIdx.x * blockDim.x + threadIdx.x;
    int t = i4 / per;
    int off = i4 - t * per;
    const float* src = (t == 0) ? s0 : (t == 1) ? s1 : (t == 2) ? s2 :
                       (t == 3) ? s3 : (t == 4) ? s4 : (t == 5) ? s5 : s6;
    float4 vv = ((const float4*)src)[off];
    __nv_bfloat162 a, b;
    a.x = __float2bfloat16(vv.x); a.y = __float2bfloat16(vv.y);
    b.x = __float2bfloat16(vv.z); b.y = __float2bfloat16(vv.w);
    __nv_bfloat162* dst = (__nv_bfloat162*)(g_wbf + (size_t)t * WSZ);
    dst[off * 2]     = a;
    dst[off * 2 + 1] = b;
}

__global__ void pe_kernel() {
    int i = blockIdx.x * blockDim.x + threadIdx.x;
    if (i < NR*(CC/2)) {
        int r = i / (CC/2);
        int j = i % (CC/2);
        float div = expf(-(float)(2*j) * (9.210340371976184f / (float)CC)); // ln(10000)/C
        float ang = (float)(WHALF - r) * div;   // rel = -(r-50)
        g_pebf[r*CC + 2*j]     = __float2bfloat16(sinf(ang));
        g_pebf[r*CC + 2*j + 1] = __float2bfloat16(cosf(ang));
    }
}

// LayerNorm: fp32 in, bf16 out. 4 rows/block, 64 threads/row (3 float4 each).
__global__ void ln_kernel(const float* __restrict__ in, __nv_bfloat16* __restrict__ out,
                          const float* __restrict__ g, const float* __restrict__ b) {
    const int tid = threadIdx.x;
    const int grp = tid >> 6;            // 0..3: row within block
    const int lt  = tid & 63;
    const int row = blockIdx.x * 4 + grp;
    const float4* xr = (const float4*)(in + (size_t)row * CC);
    float4 v0 = xr[lt], v1 = xr[lt + 64], v2 = xr[lt + 128];
    float s  = v0.x+v0.y+v0.z+v0.w + v1.x+v1.y+v1.z+v1.w + v2.x+v2.y+v2.z+v2.w;
    float s2 = v0.x*v0.x+v0.y*v0.y+v0.z*v0.z+v0.w*v0.w
             + v1.x*v1.x+v1.y*v1.y+v1.z*v1.z+v1.w*v1.w
             + v2.x*v2.x+v2.y*v2.y+v2.z*v2.z+v2.w*v2.w;
    #pragma unroll
    for (int o = 16; o; o >>= 1) {
        s  += __shfl_xor_sync(0xffffffffu, s,  o);
        s2 += __shfl_xor_sync(0xffffffffu, s2, o);
    }
    __shared__ float sh[16];
    if ((lt & 31) == 0) {
        int slot = grp * 2 + (lt >> 5);
        sh[slot] = s; sh[8 + slot] = s2;
    }
    __syncthreads();
    s  = sh[grp*2]     + sh[grp*2 + 1];
    s2 = sh[8 + grp*2] + sh[8 + grp*2 + 1];
    float mean = s * (1.f / CC);
    float var  = s2 * (1.f / CC) - mean * mean;
    float rstd = rsqrtf(var + 1e-5f);
    __nv_bfloat16* orow = out + (size_t)row * CC;
    #pragma unroll
    for (int i = 0; i < 3; i++) {
        int idx = lt + i * 64;
        float4 vv = (i == 0) ? v0 : (i == 1) ? v1 : v2;
        float4 g4 = ((const float4*)g)[idx];
        float4 b4 = ((const float4*)b)[idx];
        __nv_bfloat162 p0, p1;
        p0.x = __float2bfloat16((vv.x - mean) * rstd * g4.x + b4.x);
        p0.y = __float2bfloat16((vv.y - mean) * rstd * g4.y + b4.y);
        p1.x = __float2bfloat16((vv.z - mean) * rstd * g4.z + b4.z);
        p1.y = __float2bfloat16((vv.w - mean) * rstd * g4.w + b4.w);
        uint2 u;
        u.x = *(uint32_t*)&p0;
        u.y = *(uint32_t*)&p1;
        ((uint2*)orow)[idx] = u;
    }
}

// ---------------- mma / ldmatrix / cp.async helpers ----------------
__device__ __forceinline__ void mma_bf16(float c[4], const uint4& a, uint32_t b0, uint32_t b1) {
    asm volatile(
        "mma.sync.aligned.m16n8k16.row.col.f32.bf16.bf16.f32 "
        "{%0,%1,%2,%3}, {%4,%5,%6,%7}, {%8,%9}, {%0,%1,%2,%3};"
        : "+f"(c[0]), "+f"(c[1]), "+f"(c[2]), "+f"(c[3])
        : "r"(a.x), "r"(a.y), "r"(a.z), "r"(a.w), "r"(b0), "r"(b1));
}
__device__ __forceinline__ void ldsm_x4(uint4& d, uint32_t addr) {
    asm volatile("ldmatrix.sync.aligned.m8n8.x4.shared.b16 {%0,%1,%2,%3}, [%4];"
                 : "=r"(d.x), "=r"(d.y), "=r"(d.z), "=r"(d.w) : "r"(addr));
}
__device__ __forceinline__ void ldsm_x4_t(uint4& d, uint32_t addr) {
    asm volatile("ldmatrix.sync.aligned.m8n8.x4.trans.shared.b16 {%0,%1,%2,%3}, [%4];"
                 : "=r"(d.x), "=r"(d.y), "=r"(d.z), "=r"(d.w) : "r"(addr));
}
__device__ __forceinline__ void cp16(uint32_t dst, const void* src, int srcsize) {
    asm volatile("cp.async.cg.shared.global [%0], [%1], 16, %2;\n"
                 :: "r"(dst), "l"(src), "r"(srcsize));
}
__device__ __forceinline__ void cp_commit() {
    asm volatile("cp.async.commit_group;\n");
}
template<int N> __device__ __forceinline__ void cp_wait() {
    asm volatile("cp.async.wait_group %0;\n" :: "n"(N));
}

__device__ __forceinline__ float gelu_f(float x) {
    float x3 = x * x * x;
    return 0.5f * x * (1.f + tanhf(0.7978845608028654f * (x + 0.044715f * x3)));
}

// ---------------- bf16 tensor-core GEMM, 3-stage cp.async (R9 proven tiling) ----------------
#define AST2 20
#define BST2 36
#define STG_A (128*AST2)   // 2560 u32
#define STG_B (32*BST2)    // 1152 u32
#define GEMM_SMEM (3*(STG_A+STG_B)*4)   // 44544 bytes

template<int EPI, int OUTBF>
__device__ __forceinline__ void gemm_body(
        const __nv_bfloat16* __restrict__ A, const __nv_bfloat16* __restrict__ Bm,
        const float* __restrict__ bias, const float* __restrict__ resid,
        void* __restrict__ Cm, int M, int N, int K, int row0, int col0) {
    extern __shared__ uint32_t smu[];
    const uint32_t smem_base = (uint32_t)__cvta_generic_to_shared(smu);

    const int tid  = threadIdx.x;
    const int warp = tid >> 5;
    const int lane = tid & 31;
    const int g    = lane >> 2;
    const int t    = lane & 3;
    const int wr   = warp >> 1;
    const int wc   = warp & 1;

    float acc[2][4][4];
    #pragma unroll
    for (int i = 0; i < 2; i++)
        #pragma unroll
        for (int j = 0; j < 4; j++)
            #pragma unroll
            for (int r = 0; r < 4; r++) acc[i][j][r] = 0.f;

    const int a_r = tid >> 2, a_c = tid & 3;
    const int b_r = tid >> 3, b_c = tid & 7;

#define LOADS(s_) do {                                                              \
        const int k0_ = (s_) * 32;                                                  \
        uint32_t* Ab_ = smu + ((s_) % 3) * (STG_A + STG_B);                         \
        uint32_t* Bb_ = Ab_ + STG_A;                                                \
        _Pragma("unroll")                                                           \
        for (int i_ = 0; i_ < 2; i_++) {                                            \
            int r_ = a_r + i_ * 64;                                                 \
            int gr_ = row0 + r_;                                                    \
            int ok_ = (gr_ < M) ? 16 : 0;                                           \
            const __nv_bfloat16* src_ = A + (size_t)(ok_ ? gr_ : 0) * K + k0_ + a_c * 8; \
            cp16((uint32_t)__cvta_generic_to_shared(Ab_ + r_ * AST2 + a_c * 4), src_, ok_); \
        }                                                                           \
        {                                                                           \
            const __nv_bfloat16* src_ = Bm + (size_t)(k0_ + b_r) * N + col0 + b_c * 8;   \
            cp16((uint32_t)__cvta_generic_to_shared(Bb_ + b_r * BST2 + b_c * 4), src_, 16); \
        }                                                                           \
    } while (0)

    const int steps = K >> 5;
    LOADS(0); cp_commit();
    LOADS(1); cp_commit();

    const int a_lane_off = (lane & 15) * AST2 + (lane >> 4) * 4;
    const int b_lane_off = (lane & 15) * BST2 + wc * 16 + (lane >> 4) * 4;

    for (int s = 0; s < steps; s++) {
        cp_wait<1>();
        __syncthreads();
        if (s + 2 < steps) LOADS(s + 2);
        cp_commit();

        const uint32_t bufo = (uint32_t)((s % 3) * (STG_A + STG_B));
        const uint32_t abase = smem_base + (bufo + wr * 32 * AST2 + a_lane_off) * 4;
        const uint32_t bbase = smem_base + (bufo + STG_A + b_lane_off) * 4;

        #pragma unroll
        for (int ch = 0; ch < 2; ch++) {
            uint4 af[2];
            #pragma unroll
            for (int i = 0; i < 2; i++)
                ldsm_x4(af[i], abase + (i * 16 * AST2 + ch * 8) * 4);
            uint4 bq[2];
            #pragma unroll
            for (int jj = 0; jj < 2; jj++)
                ldsm_x4_t(bq[jj], bbase + (ch * 16 * BST2 + jj * 8) * 4);
            #pragma unroll
            for (int i = 0; i < 2; i++) {
                mma_bf16(acc[i][0], af[i], bq[0].x, bq[0].y);
                mma_bf16(acc[i][1], af[i], bq[0].z, bq[0].w);
                mma_bf16(acc[i][2], af[i], bq[1].x, bq[1].y);
                mma_bf16(acc[i][3], af[i], bq[1].z, bq[1].w);
            }
        }
    }
#undef LOADS

    __syncthreads();

    #pragma unroll
    for (int i = 0; i < 2; i++) {
        int rbase = row0 + wr * 32 + i * 16 + g;
        #pragma unroll
        for (int j = 0; j < 4; j++) {
            int col = col0 + wc * 32 + j * 8 + t * 2;
            float bx = 0.f, by = 0.f;
            if (bias) { bx = bias[col]; by = bias[col + 1]; }
            #pragma unroll
            for (int hh = 0; hh < 2; hh++) {
                int row = rbase + hh * 8;
                if (row < M) {
                    float c0 = acc[i][j][hh * 2 + 0] + bx;
                    float c1 = acc[i][j][hh * 2 + 1] + by;
                    if (EPI == 1) { c0 = gelu_f(c0); c1 = gelu_f(c1); }
                    if (EPI == 2) {
                        float2 rv = *(const float2*)(resid + (size_t)row * N + col);
                        c0 += rv.x; c1 += rv.y;
                    }
                    if (OUTBF) {
                        __nv_bfloat162 p;
                        p.x = __float2bfloat16(c0);
                        p.y = __float2bfloat16(c1);
                        *(__nv_bfloat162*)((__nv_bfloat16*)Cm + (size_t)row * N + col) = p;
                    } else {
                        *(float2*)((float*)Cm + (size_t)row * N + col) = make_float2(c0, c1);
                    }
                }
            }
        }
    }
}

template<int EPI, int OUTBF>
__global__ void __launch_bounds__(256)
tgemm_kernel(const __nv_bfloat16* __restrict__ A, const __nv_bfloat16* __restrict__ Bm,
             const float* __restrict__ bias, const float* __restrict__ resid,
             void* __restrict__ Cm, int M, int N, int K) {
    gemm_body<EPI, OUTBF>(A, Bm, bias, resid, Cm, M, N, K,
                          blockIdx.y * 128, blockIdx.x * 64);
}

// fused QKV + Wp: blockIdx.x in [0,48). [0,36): sel=x/12 picks {q,k,v};
// [36,48): the tiny pe@Wp GEMM (M=101) on blockIdx.y==0 only.
__global__ void __launch_bounds__(256)
qkv_kernel(const __nv_bfloat16* __restrict__ A,
           const __nv_bfloat16* __restrict__ Bq, const __nv_bfloat16* __restrict__ Bk,
           const __nv_bfloat16* __restrict__ Bv, const __nv_bfloat16* __restrict__ Bp,
           const float* __restrict__ bq, const float* __restrict__ bk,
           const float* __restrict__ bv,
           __nv_bfloat16* __restrict__ Cq, __nv_bfloat16* __restrict__ Ck,
           __nv_bfloat16* __restrict__ Cv,
           const __nv_bfloat16* __restrict__ pe, __nv_bfloat16* __restrict__ Cp) {
    int xx = blockIdx.x;
    if (xx < 36) {
        int sel = xx / 12;
        int colblk = xx % 12;
        const __nv_bfloat16* Bm = (sel == 0) ? Bq : (sel == 1) ? Bk : Bv;
        const float* bias       = (sel == 0) ? bq : (sel == 1) ? bk : bv;
        __nv_bfloat16* Cm       = (sel == 0) ? Cq : (sel == 1) ? Ck : Cv;
        gemm_body<0, 1>(A, Bm, bias, nullptr, Cm, BT, CC, CC,
                        blockIdx.y * 128, colblk * 64);
    } else {
        if (blockIdx.y != 0) return;
        int colblk = xx - 36;
        gemm_body<0, 1>(pe, Bp, nullptr, nullptr, Cp, NR, CC, CC,
                        0, colblk * 64);
    }
}

// ---------------- banded rel-pos attention (bf16 tensor-core, TQ=32) ----------------
// Per block: (b, h, 32 queries). Window rows staged: 32+100 = 132 (padded to 144).
//  GEMM1: S1'[32][136] = QU(32x64) @ K^T       S[qi][r] = S1'[qi][qi+r]
//  GEMM2: SC'[32][104] = QV(32x64) @ P^T
//  combine+mask -> softmax -> scatter bf16 into shifted AT[32][152] (144 used)
//  GEMM3: O[32][64] = AT @ V(144x64)
// u32 strides: K/V/P/QU/QV = 36 (mod32=4), S1 = 140, AT = 76 (12g+t distinct).
#define TQ 32
#define SRW 144           // staged k/v rows (132 used, padded to 144 = 9*16)

#define U_KV 0            // 144 x 36
#define U_QU 5184         // 32 x 36
#define U_QV 6336         // 32 x 36
#define U_PS 7488         // 104 x 36
#define U_S1 11232        // fp32 32 x 140
#define U_SC 15712        // fp32 32 x 104
#define U_AT 19040        // 32 x 76 u32 (= 152 bf16 cols)
#define ATTN_U32 21472
#define ATTN_SMEM_BYTES (ATTN_U32*4)

__global__ void __launch_bounds__(256)
attn_kernel(const __nv_bfloat16* __restrict__ q, const __nv_bfloat16* __restrict__ k,
            const __nv_bfloat16* __restrict__ v, const __nv_bfloat16* __restrict__ pc,
            const float* __restrict__ pu, const float* __restrict__ pv,
            __nv_bfloat16* __restrict__ o) {
    extern __shared__ uint32_t su[];
    uint32_t* KV  = su + U_KV;
    uint32_t* QUb = su + U_QU;
    uint32_t* QVb = su + U_QV;
    uint32_t* PSb = su + U_PS;
    float*    S1  = (float*)(su + U_S1);
    float*    SC  = (float*)(su + U_SC);
    uint32_t* AT  = su + U_AT;
    const uint32_t smem_base = (uint32_t)__cvta_generic_to_shared(su);

    const int b  = blockIdx.z;
    const int h  = blockIdx.y;
    const int t0 = blockIdx.x * TQ;
    const int sb = t0 - WHALF;
    const int tid = threadIdx.x;
    const int warp = tid >> 5, lane = tid & 31;
    const int g = lane >> 2, t4 = lane & 3;

    // ---- phase 1: stage QU/QV (32x64), K (144 rows), P (104 rows)
    for (int e = tid; e < TQ * 32; e += 256) {
        int qi = e >> 5, cu = e & 31;
        int tt = t0 + qi;
        float f0 = 0.f, f1 = 0.f;
        if (tt < TT) {
            uint32_t raw = *(const uint32_t*)(q + ((size_t)(b*TT+tt))*CC + h*DKK + cu*2);
            __nv_bfloat162 p = *(__nv_bfloat162*)&raw;
            f0 = __bfloat162float(p.x); f1 = __bfloat162float(p.y);
        }
        float u0 = pu[h*DKK + cu*2], u1 = pu[h*DKK + cu*2 + 1];
        float w0 = pv[h*DKK + cu*2], w1 = pv[h*DKK + cu*2 + 1];
        __nv_bfloat162 a, c;
        a.x = __float2bfloat16(f0 + u0); a.y = __float2bfloat16(f1 + u1);
        c.x = __float2bfloat16(f0 + w0); c.y = __float2bfloat16(f1 + w1);
        QUb[qi*36 + cu] = *(uint32_t*)&a;
        QVb[qi*36 + cu] = *(uint32_t*)&c;
    }
    for (int e = tid; e < SRW * 8; e += 256) {
        int si = e >> 3, c = e & 7;
        int s = sb + si;
        uint4 kk = make_uint4(0,0,0,0);
        if (si < 132 && s >= 0 && s < TT)
            kk = *(const uint4*)(k + ((size_t)(b*TT+s))*CC + h*DKK + c*8);
        *(uint4*)(KV + si*36 + c*4) = kk;
    }
    for (int e = tid; e < 104 * 8; e += 256) {
        int r = e >> 3, c = e & 7;
        uint4 pp = make_uint4(0,0,0,0);
        if (r < NR) pp = *(const uint4*)(pc + (size_t)r*CC + h*DKK + c*8);
        *(uint4*)(PSb + r*36 + c*4) = pp;
    }
    __syncthreads();

    // ---- phase 2: score GEMMs. units = mt (2) x nt ; A fragments hoisted per source.
    {
        uint4 af[2][4];
        #pragma unroll
        for (int mt = 0; mt < 2; mt++)
            #pragma unroll
            for (int ch = 0; ch < 4; ch++) {
                af[mt][ch].x = QUb[(mt*16+g)*36 + ch*8 + t4];
                af[mt][ch].y = QUb[(mt*16+g+8)*36 + ch*8 + t4];
                af[mt][ch].z = QUb[(mt*16+g)*36 + ch*8 + t4 + 4];
                af[mt][ch].w = QUb[(mt*16+g+8)*36 + ch*8 + t4 + 4];
            }
        // GEMM1: 2 mt x 17 nt = 34 units (cols 0..135)
        for (int u = warp; u < 34; u += 8) {
            int mt = u & 1, nt = u >> 1;
            float c[4] = {0.f, 0.f, 0.f, 0.f};
            #pragma unroll
            for (int ch = 0; ch < 4; ch++) {
                uint32_t b0 = KV[(nt*8+g)*36 + ch*8 + t4];
                uint32_t b1 = KV[(nt*8+g)*36 + ch*8 + t4 + 4];
                mma_bf16(c, af[mt][ch], b0, b1);
            }
            *(float2*)(S1 + (mt*16+g)*140 + nt*8 + 2*t4)   = make_float2(c[0], c[1]);
            *(float2*)(S1 + (mt*16+g+8)*140 + nt*8 + 2*t4) = make_float2(c[2], c[3]);
        }
        #pragma unroll
        for (int mt = 0; mt < 2; mt++)
            #pragma unroll
            for (int ch = 0; ch < 4; ch++) {
                af[mt][ch].x = QVb[(mt*16+g)*36 + ch*8 + t4];
                af[mt][ch].y = QVb[(mt*16+g+8)*36 + ch*8 + t4];
                af[mt][ch].z = QVb[(mt*16+g)*36 + ch*8 + t4 + 4];
                af[mt][ch].w = QVb[(mt*16+g+8)*36 + ch*8 + t4 + 4];
            }
        // GEMM2: 2 mt x 13 nt = 26 units (cols 0..103)
        for (int u = warp; u < 26; u += 8) {
            int mt = u & 1, nt = u >> 1;
            float c[4] = {0.f, 0.f, 0.f, 0.f};
            #pragma unroll
            for (int ch = 0; ch < 4; ch++) {
                uint32_t b0 = PSb[(nt*8+g)*36 + ch*8 + t4];
                uint32_t b1 = PSb[(nt*8+g)*36 + ch*8 + t4 + 4];
                mma_bf16(c, af[mt][ch], b0, b1);
            }
            *(float2*)(SC + (mt*16+g)*104 + nt*8 + 2*t4)   = make_float2(c[0], c[1]);
            *(float2*)(SC + (mt*16+g+8)*104 + nt*8 + 2*t4) = make_float2(c[2], c[3]);
        }
    }
    __syncthreads();

    // ---- phase 3a: combine+mask -> SC ; zero AT ; stage V (overwrites K)
    for (int e = tid; e < TQ * NR; e += 256) {
        int qi = e & 31, r = e >> 5;
        int tt = t0 + qi, s = tt + r - WHALF;
        float val = -1e30f;
        if (tt < TT && s >= 0 && s < TT)
            val = (S1[qi*140 + qi + r] + SC[qi*104 + r]) * 0.125f;
        SC[qi*104 + r] = val;
    }
    for (int e = tid; e < TQ * 76; e += 256) AT[e] = 0u;
    for (int e = tid; e < SRW * 8; e += 256) {
        int si = e >> 3, c = e & 7;
        int s = sb + si;
        uint4 vv = make_uint4(0,0,0,0);
        if (si < 132 && s >= 0 && s < TT)
            vv = *(const uint4*)(v + ((size_t)(b*TT+s))*CC + h*DKK + c*8);
        *(uint4*)(KV + si*36 + c*4) = vv;
    }
    __syncthreads();

    // ---- phase 3b: softmax (serial, 32 rows in parallel)
    if (tid < TQ) {
        float* srow = SC + tid * 104;
        float m = -1e30f;
        for (int r = 0; r < NR; r++) m = fmaxf(m, srow[r]);
        float sum = 0.f;
        for (int r = 0; r < NR; r++) { float ev = __expf(srow[r] - m); srow[r] = ev; sum += ev; }
        float inv = 1.f / sum;
        for (int r = 0; r < NR; r++) srow[r] *= inv;
    }
    __syncthreads();

    // ---- phase 3c: scatter bf16 weights into shifted AT (152 bf16 stride)
    for (int e = tid; e < TQ * NR; e += 256) {
        int qi = e & 31, r = e >> 5;
        ((__nv_bfloat16*)AT)[qi*152 + qi + r] = __float2bfloat16(SC[qi*104 + r]);
    }
    __syncthreads();

    // ---- phase 4: O = AT(32x144) @ V(144x64); warp w: mt = w>>2, n16 = (w&3)*16
    {
        int mt = warp >> 2;
        int n0 = (warp & 3) * 16;
        float c0[4] = {0.f,0.f,0.f,0.f};
        float c1[4] = {0.f,0.f,0.f,0.f};
        uint32_t vbase = smem_base + (U_KV + (lane & 15)*36 + (n0 >> 1) + (lane >> 4)*4) * 4;
        #pragma unroll
        for (int ch = 0; ch < 9; ch++) {
            uint4 a;
            a.x = AT[(mt*16+g)*76 + ch*8 + t4];
            a.y = AT[(mt*16+g+8)*76 + ch*8 + t4];
            a.z = AT[(mt*16+g)*76 + ch*8 + t4 + 4];
            a.w = AT[(mt*16+g+8)*76 + ch*8 + t4 + 4];
            uint4 bq;
            ldsm_x4_t(bq, vbase + (ch * 16 * 36) * 4);
            mma_bf16(c0, a, bq.x, bq.y);
            mma_bf16(c1, a, bq.z, bq.w);
        }
        int tg0 = t0 + mt*16 + g, tg1 = tg0 + 8;
        if (tg0 < TT) {
            __nv_bfloat16* orow = o + ((size_t)(b*TT+tg0))*CC + h*DKK;
            __nv_bfloat162 p;
            p.x = __float2bfloat16(c0[0]); p.y = __float2bfloat16(c0[1]);
            *(__nv_bfloat162*)(orow + n0 + 2*t4) = p;
            p.x = __float2bfloat16(c1[0]); p.y = __float2bfloat16(c1[1]);
            *(__nv_bfloat162*)(orow + n0 + 8 + 2*t4) = p;
        }
        if (tg1 < TT) {
            __nv_bfloat16* orow = o + ((size_t)(b*TT+tg1))*CC + h*DKK;
            __nv_bfloat162 p;
            p.x = __float2bfloat16(c0[2]); p.y = __float2bfloat16(c0[3]);
            *(__nv_bfloat162*)(orow + n0 + 2*t4) = p;
            p.x = __float2bfloat16(c1[2]); p.y = __float2bfloat16(c1[3]);
            *(__nv_bfloat162*)(orow + n0 + 8 + 2*t4) = p;
        }
    }
}

// ---------------- driver ----------------
extern "C" void kernel_launch(void* const* d_in, const int* in_sizes, int n_in,
                              void* d_out, int out_size) {
    const float* x    = (const float*)d_in[0];
    const float* Wq   = (const float*)d_in[1];
    const float* bq   = (const float*)d_in[2];
    const float* Wk   = (const float*)d_in[3];
    const float* bk   = (const float*)d_in[4];
    const float* Wv   = (const float*)d_in[5];
    const float* bv   = (const float*)d_in[6];
    const float* Wo   = (const float*)d_in[7];
    const float* bo   = (const float*)d_in[8];
    const float* Wp   = (const float*)d_in[9];
    const float* pu   = (const float*)d_in[10];
    const float* pvv  = (const float*)d_in[11];
    const float* ln1g = (const float*)d_in[12];
    const float* ln1b = (const float*)d_in[13];
    const float* ln2g = (const float*)d_in[14];
    const float* ln2b = (const float*)d_in[15];
    const float* W1   = (const float*)d_in[16];
    const float* b1   = (const float*)d_in[17];
    const float* W2   = (const float*)d_in[18];
    const float* b2   = (const float*)d_in[19];
    // d_in[20] = att_mask: fixed band |i-j|>50, handled analytically.

    float* h;
    __nv_bfloat16 *ybf, *obf, *qb, *kb, *vb, *pcb, *pebf, *wbf;
    cudaGetSymbolAddress((void**)&h,    g_h);
    cudaGetSymbolAddress((void**)&ybf,  g_ybf);
    cudaGetSymbolAddress((void**)&obf,  g_obf);
    cudaGetSymbolAddress((void**)&qb,   g_qb);
    cudaGetSymbolAddress((void**)&kb,   g_kb);
    cudaGetSymbolAddress((void**)&vb,   g_vb);
    cudaGetSymbolAddress((void**)&pcb,  g_pcb);
    cudaGetSymbolAddress((void**)&pebf, g_pebf);
    cudaGetSymbolAddress((void**)&wbf,  g_wbf);

    cudaFuncSetAttribute(tgemm_kernel<1,1>, cudaFuncAttributeMaxDynamicSharedMemorySize, GEMM_SMEM);
    cudaFuncSetAttribute(tgemm_kernel<2,0>, cudaFuncAttributeMaxDynamicSharedMemorySize, GEMM_SMEM);
    cudaFuncSetAttribute(qkv_kernel,        cudaFuncAttributeMaxDynamicSharedMemorySize, GEMM_SMEM);
    cudaFuncSetAttribute(attn_kernel,       cudaFuncAttributeMaxDynamicSharedMemorySize, ATTN_SMEM_BYTES);

    f2b_all_kernel<<<7 * (WSZ / 4) / 256, 256>>>(Wq, Wk, Wv, Wo, Wp, W1, W2);
    init_h_kernel<<<(BT*CC + 255) / 256, 256>>>(x);
    pe_kernel<<<(NR*(CC/2) + 255) / 256, 256>>>();

    dim3 gBig(CC / 64, (BT + 127) / 128);        // (12, 32)
    dim3 gQKV(48, (BT + 127) / 128);             // (48, 32): qkv + fused Wp
    dim3 gAtt((TT + TQ - 1) / TQ, HH, BB);       // (32, 12, 4)

    for (int l = 0; l < LNUM; l++) {
        size_t wOff = (size_t)l * CC * CC;
        size_t bOff = (size_t)l * CC;

        ln_kernel<<<BT / 4, 256>>>(h, ybf, ln1g + bOff, ln1b + bOff);
        qkv_kernel<<<gQKV, 256, GEMM_SMEM>>>(ybf,
            wbf + 0*WSZ + wOff, wbf + 1*WSZ + wOff, wbf + 2*WSZ + wOff,
            wbf + 4*WSZ + wOff,
            bq + bOff, bk + bOff, bv + bOff, qb, kb, vb, pebf, pcb);
        attn_kernel<<<gAtt, 256, ATTN_SMEM_BYTES>>>(qb, kb, vb, pcb, pu + bOff, pvv + bOff, obf);
        tgemm_kernel<2,0><<<gBig, 256, GEMM_SMEM>>>(obf, wbf + 3*WSZ + wOff,
            bo + bOff, h, h, BT, CC, CC);
        ln_kernel<<<BT / 4, 256>>>(h, ybf, ln2g + bOff, ln2b + bOff);
        tgemm_kernel<1,1><<<gBig, 256, GEMM_SMEM>>>(ybf, wbf + 5*WSZ + wOff,
            b1 + bOff, nullptr, obf, BT, CC, CC);
        void* outp = (l == LNUM - 1) ? d_out : (void*)h;
        tgemm_kernel<2,0><<<gBig, 256, GEMM_SMEM>>>(obf, wbf + 6*WSZ + wOff,
            b2 + bOff, h, outp, BT, CC, CC);
    }
}

// round 15
// speedup vs baseline: 1.1245x; 1.1245x over previous
#include <cuda_runtime.h>
#include <cuda_bf16.h>
#include <math.h>
#include <stdint.h>

// ---------------- problem constants ----------------
#define LNUM 2
#define BB   4
#define TT   1000
#define CC   768
#define HH   12
#define DKK  64
#define WHALF 50         // band half-width (WIN//2)
#define NR   101         // relative positions actually reachable: -50..50
#define BT   (BB*TT)     // 4000 rows
#define WSZ  (LNUM*CC*CC)

// ---------------- device scratch (no allocs allowed) ----------------
__device__ float g_h[BT*CC];
__device__ __nv_bfloat16 g_ybf[BT*CC];        // LN output (GEMM A operand)
__device__ __nv_bfloat16 g_obf[BT*CC];        // attn out / gelu out (GEMM A operand)
__device__ __nv_bfloat16 g_qb[BT*CC];
__device__ __nv_bfloat16 g_kb[BT*CC];
__device__ __nv_bfloat16 g_vb[BT*CC];
__device__ __nv_bfloat16 g_pcb[NR*CC];        // pe @ Wp[l], bf16
__device__ __nv_bfloat16 g_pebf[NR*CC];       // positional table, bf16
__device__ __nv_bfloat16 g_wbf[7*WSZ];        // bf16 weights: Wq,Wk,Wv,Wo,Wp,W1,W2

// ---------------- fused setup: f2b (all 7 weights) + init_h + pe ----------------
#define F2B_BLKS  (7 * (WSZ / 4) / 256)            // 8064
#define INIT_BLKS ((BT * CC / 4) / 256)            // 3000
#define PE_BLKS   ((NR * (CC/2) + 255) / 256)      // 152
#define SETUP_BLKS (F2B_BLKS + INIT_BLKS + PE_BLKS)

__global__ void setup_kernel(const float* __restrict__ x,
                             const float* __restrict__ s0, const float* __restrict__ s1,
                             const float* __restrict__ s2, const float* __restrict__ s3,
                             const float* __restrict__ s4, const float* __restrict__ s5,
                             const float* __restrict__ s6) {
    int bx = blockIdx.x;
    if (bx < F2B_BLKS) {
        const int per = WSZ / 4;
        int i4 = bx * 256 + threadIdx.x;
        int t = i4 / per;
        int off = i4 - t * per;
        const float* src = (t == 0) ? s0 : (t == 1) ? s1 : (t == 2) ? s2 :
                           (t == 3) ? s3 : (t == 4) ? s4 : (t == 5) ? s5 : s6;
        float4 vv = ((const float4*)src)[off];
        __nv_bfloat162 a, b;
        a.x = __float2bfloat16(vv.x); a.y = __float2bfloat16(vv.y);
        b.x = __float2bfloat16(vv.z); b.y = __float2bfloat16(vv.w);
        __nv_bfloat162* dst = (__nv_bfloat162*)(g_wbf + (size_t)t * WSZ);
        dst[off * 2]     = a;
        dst[off * 2 + 1] = b;
    } else if (bx < F2B_BLKS + INIT_BLKS) {
        int i4 = (bx - F2B_BLKS) * 256 + threadIdx.x;
        float4 vv = ((const float4*)x)[i4];
        const float sc = 27.712812921102035f;  // sqrt(768)
        ((float4*)g_h)[i4] = make_float4(vv.x*sc, vv.y*sc, vv.z*sc, vv.w*sc);
    } else {
        int i = (bx - F2B_BLKS - INIT_BLKS) * 256 + threadIdx.x;
        if (i < NR*(CC/2)) {
            int r = i / (CC/2);
            int j = i % (CC/2);
            float div = expf(-(float)(2*j) * (9.210340371976184f / (float)CC));
            float ang = (float)(WHALF - r) * div;
            g_pebf[r*CC + 2*j]     = __float2bfloat16(sinf(ang));
            g_pebf[r*CC + 2*j + 1] = __float2bfloat16(cosf(ang));
        }
    }
}

// LayerNorm: fp32 in, bf16 out. 1 row/block, 192 threads (all active).
__global__ void __launch_bounds__(192)
ln_kernel(const float* __restrict__ in, __nv_bfloat16* __restrict__ out,
          const float* __restrict__ g, const float* __restrict__ b) {
    const int row = blockIdx.x;
    const int tid = threadIdx.x;
    const float4* xr = (const float4*)(in + (size_t)row * CC);
    float4 vv = xr[tid];
    float s  = vv.x + vv.y + vv.z + vv.w;
    float s2 = vv.x*vv.x + vv.y*vv.y + vv.z*vv.z + vv.w*vv.w;
    __shared__ float sh[16];
    #pragma unroll
    for (int o = 16; o; o >>= 1) {
        s  += __shfl_xor_sync(0xffffffffu, s,  o);
        s2 += __shfl_xor_sync(0xffffffffu, s2, o);
    }
    int w = tid >> 5;
    if ((tid & 31) == 0) { sh[w] = s; sh[8 + w] = s2; }
    __syncthreads();
    s = 0.f; s2 = 0.f;
    #pragma unroll
    for (int i = 0; i < 6; i++) { s += sh[i]; s2 += sh[8 + i]; }
    float mean = s * (1.f / CC);
    float var  = s2 * (1.f / CC) - mean * mean;
    float rstd = rsqrtf(var + 1e-5f);
    float4 g4 = ((const float4*)g)[tid];
    float4 b4 = ((const float4*)b)[tid];
    __nv_bfloat162 p0, p1;
    p0.x = __float2bfloat16((vv.x - mean) * rstd * g4.x + b4.x);
    p0.y = __float2bfloat16((vv.y - mean) * rstd * g4.y + b4.y);
    p1.x = __float2bfloat16((vv.z - mean) * rstd * g4.z + b4.z);
    p1.y = __float2bfloat16((vv.w - mean) * rstd * g4.w + b4.w);
    uint2 u;
    u.x = *(uint32_t*)&p0;
    u.y = *(uint32_t*)&p1;
    ((uint2*)(out + (size_t)row * CC))[tid] = u;
}

// ---------------- mma / ldmatrix / cp.async helpers ----------------
__device__ __forceinline__ void mma_bf16(float c[4], const uint4& a, uint32_t b0, uint32_t b1) {
    asm volatile(
        "mma.sync.aligned.m16n8k16.row.col.f32.bf16.bf16.f32 "
        "{%0,%1,%2,%3}, {%4,%5,%6,%7}, {%8,%9}, {%0,%1,%2,%3};"
        : "+f"(c[0]), "+f"(c[1]), "+f"(c[2]), "+f"(c[3])
        : "r"(a.x), "r"(a.y), "r"(a.z), "r"(a.w), "r"(b0), "r"(b1));
}
__device__ __forceinline__ void ldsm_x4(uint4& d, uint32_t addr) {
    asm volatile("ldmatrix.sync.aligned.m8n8.x4.shared.b16 {%0,%1,%2,%3}, [%4];"
                 : "=r"(d.x), "=r"(d.y), "=r"(d.z), "=r"(d.w) : "r"(addr));
}
__device__ __forceinline__ void ldsm_x4_t(uint4& d, uint32_t addr) {
    asm volatile("ldmatrix.sync.aligned.m8n8.x4.trans.shared.b16 {%0,%1,%2,%3}, [%4];"
                 : "=r"(d.x), "=r"(d.y), "=r"(d.z), "=r"(d.w) : "r"(addr));
}
__device__ __forceinline__ void cp16(uint32_t dst, const void* src, int srcsize) {
    asm volatile("cp.async.cg.shared.global [%0], [%1], 16, %2;\n"
                 :: "r"(dst), "l"(src), "r"(srcsize));
}
__device__ __forceinline__ void cp_commit() {
    asm volatile("cp.async.commit_group;\n");
}
template<int N> __device__ __forceinline__ void cp_wait() {
    asm volatile("cp.async.wait_group %0;\n" :: "n"(N));
}

__device__ __forceinline__ float gelu_f(float x) {
    float x3 = x * x * x;
    return 0.5f * x * (1.f + tanhf(0.7978845608028654f * (x + 0.044715f * x3)));
}

// ---------------- bf16 tensor-core GEMM, 3-stage cp.async (R12 proven) ----------------
#define AST2 20
#define BST2 36
#define STG_A (128*AST2)   // 2560 u32
#define STG_B (32*BST2)    // 1152 u32
#define GEMM_SMEM (3*(STG_A+STG_B)*4)   // 44544 bytes

template<int EPI, int OUTBF>
__device__ __forceinline__ void gemm_body(
        const __nv_bfloat16* __restrict__ A, const __nv_bfloat16* __restrict__ Bm,
        const float* __restrict__ bias, const float* __restrict__ resid,
        void* __restrict__ Cm, int M, int N, int K, int row0, int col0) {
    extern __shared__ uint32_t smu[];
    const uint32_t smem_base = (uint32_t)__cvta_generic_to_shared(smu);

    const int tid  = threadIdx.x;
    const int warp = tid >> 5;
    const int lane = tid & 31;
    const int g    = lane >> 2;
    const int t    = lane & 3;
    const int wr   = warp >> 1;
    const int wc   = warp & 1;

    float acc[2][4][4];
    #pragma unroll
    for (int i = 0; i < 2; i++)
        #pragma unroll
        for (int j = 0; j < 4; j++)
            #pragma unroll
            for (int r = 0; r < 4; r++) acc[i][j][r] = 0.f;

    const int a_r = tid >> 2, a_c = tid & 3;
    const int b_r = tid >> 3, b_c = tid & 7;

#define LOADS(s_) do {                                                              \
        const int k0_ = (s_) * 32;                                                  \
        uint32_t* Ab_ = smu + ((s_) % 3) * (STG_A + STG_B);                         \
        uint32_t* Bb_ = Ab_ + STG_A;                                                \
        _Pragma("unroll")                                                           \
        for (int i_ = 0; i_ < 2; i_++) {                                            \
            int r_ = a_r + i_ * 64;                                                 \
            int gr_ = row0 + r_;                                                    \
            int ok_ = (gr_ < M) ? 16 : 0;                                           \
            const __nv_bfloat16* src_ = A + (size_t)(ok_ ? gr_ : 0) * K + k0_ + a_c * 8; \
            cp16((uint32_t)__cvta_generic_to_shared(Ab_ + r_ * AST2 + a_c * 4), src_, ok_); \
        }                                                                           \
        {                                                                           \
            const __nv_bfloat16* src_ = Bm + (size_t)(k0_ + b_r) * N + col0 + b_c * 8;   \
            cp16((uint32_t)__cvta_generic_to_shared(Bb_ + b_r * BST2 + b_c * 4), src_, 16); \
        }                                                                           \
    } while (0)

    const int steps = K >> 5;
    LOADS(0); cp_commit();
    LOADS(1); cp_commit();

    const int a_lane_off = (lane & 15) * AST2 + (lane >> 4) * 4;
    const int b_lane_off = (lane & 15) * BST2 + wc * 16 + (lane >> 4) * 4;

    for (int s = 0; s < steps; s++) {
        cp_wait<1>();
        __syncthreads();
        if (s + 2 < steps) LOADS(s + 2);
        cp_commit();

        const uint32_t bufo = (uint32_t)((s % 3) * (STG_A + STG_B));
        const uint32_t abase = smem_base + (bufo + wr * 32 * AST2 + a_lane_off) * 4;
        const uint32_t bbase = smem_base + (bufo + STG_A + b_lane_off) * 4;

        #pragma unroll
        for (int ch = 0; ch < 2; ch++) {
            uint4 af[2];
            #pragma unroll
            for (int i = 0; i < 2; i++)
                ldsm_x4(af[i], abase + (i * 16 * AST2 + ch * 8) * 4);
            uint4 bq[2];
            #pragma unroll
            for (int jj = 0; jj < 2; jj++)
                ldsm_x4_t(bq[jj], bbase + (ch * 16 * BST2 + jj * 8) * 4);
            #pragma unroll
            for (int i = 0; i < 2; i++) {
                mma_bf16(acc[i][0], af[i], bq[0].x, bq[0].y);
                mma_bf16(acc[i][1], af[i], bq[0].z, bq[0].w);
                mma_bf16(acc[i][2], af[i], bq[1].x, bq[1].y);
                mma_bf16(acc[i][3], af[i], bq[1].z, bq[1].w);
            }
        }
    }
#undef LOADS

    __syncthreads();

    #pragma unroll
    for (int i = 0; i < 2; i++) {
        int rbase = row0 + wr * 32 + i * 16 + g;
        #pragma unroll
        for (int j = 0; j < 4; j++) {
            int col = col0 + wc * 32 + j * 8 + t * 2;
            float bx = 0.f, by = 0.f;
            if (bias) { bx = bias[col]; by = bias[col + 1]; }
            #pragma unroll
            for (int hh = 0; hh < 2; hh++) {
                int row = rbase + hh * 8;
                if (row < M) {
                    float c0 = acc[i][j][hh * 2 + 0] + bx;
                    float c1 = acc[i][j][hh * 2 + 1] + by;
                    if (EPI == 1) { c0 = gelu_f(c0); c1 = gelu_f(c1); }
                    if (EPI == 2) {
                        float2 rv = *(const float2*)(resid + (size_t)row * N + col);
                        c0 += rv.x; c1 += rv.y;
                    }
                    if (OUTBF) {
                        __nv_bfloat162 p;
                        p.x = __float2bfloat16(c0);
                        p.y = __float2bfloat16(c1);
                        *(__nv_bfloat162*)((__nv_bfloat16*)Cm + (size_t)row * N + col) = p;
                    } else {
                        *(float2*)((float*)Cm + (size_t)row * N + col) = make_float2(c0, c1);
                    }
                }
            }
        }
    }
}

template<int EPI, int OUTBF>
__global__ void __launch_bounds__(256)
tgemm_kernel(const __nv_bfloat16* __restrict__ A, const __nv_bfloat16* __restrict__ Bm,
             const float* __restrict__ bias, const float* __restrict__ resid,
             void* __restrict__ Cm, int M, int N, int K) {
    gemm_body<EPI, OUTBF>(A, Bm, bias, resid, Cm, M, N, K,
                          blockIdx.y * 128, blockIdx.x * 64);
}

// fused QKV + Wp: blockIdx.x in [0,48). [0,36): sel=x/12 picks {q,k,v};
// [36,48): the tiny pe@Wp GEMM (M=101) on blockIdx.y==0 only.
__global__ void __launch_bounds__(256)
qkv_kernel(const __nv_bfloat16* __restrict__ A,
           const __nv_bfloat16* __restrict__ Bq, const __nv_bfloat16* __restrict__ Bk,
           const __nv_bfloat16* __restrict__ Bv, const __nv_bfloat16* __restrict__ Bp,
           const float* __restrict__ bq, const float* __restrict__ bk,
           const float* __restrict__ bv,
           __nv_bfloat16* __restrict__ Cq, __nv_bfloat16* __restrict__ Ck,
           __nv_bfloat16* __restrict__ Cv,
           const __nv_bfloat16* __restrict__ pe, __nv_bfloat16* __restrict__ Cp) {
    int xx = blockIdx.x;
    if (xx < 36) {
        int sel = xx / 12;
        int colblk = xx % 12;
        const __nv_bfloat16* Bm = (sel == 0) ? Bq : (sel == 1) ? Bk : Bv;
        const float* bias       = (sel == 0) ? bq : (sel == 1) ? bk : bv;
        __nv_bfloat16* Cm       = (sel == 0) ? Cq : (sel == 1) ? Ck : Cv;
        gemm_body<0, 1>(A, Bm, bias, nullptr, Cm, BT, CC, CC,
                        blockIdx.y * 128, colblk * 64);
    } else {
        if (blockIdx.y != 0) return;
        int colblk = xx - 36;
        gemm_body<0, 1>(pe, Bp, nullptr, nullptr, Cp, NR, CC, CC,
                        0, colblk * 64);
    }
}

// ---------------- banded rel-pos attention (bf16 tensor-core, TQ=16, R12 proven) ----------------
#define TQ 16

#define U_KV 0            // 128 rows x 36 u32 (K, then V)
#define U_QU 4608         // 16 x 36
#define U_QV 5184         // 16 x 36
#define U_PS 5760         // 104 x 36
#define U_S1 9504         // fp32 16 x 132
#define U_SC 11616        // fp32 16 x 104
#define U_AT 13280        // bf16 16 x 68 u32 (= 136 bf16 cols)
#define ATTN_U32 14368
#define ATTN_SMEM_BYTES (ATTN_U32*4)

__global__ void __launch_bounds__(256)
attn_kernel(const __nv_bfloat16* __restrict__ q, const __nv_bfloat16* __restrict__ k,
            const __nv_bfloat16* __restrict__ v, const __nv_bfloat16* __restrict__ pc,
            const float* __restrict__ pu, const float* __restrict__ pv,
            __nv_bfloat16* __restrict__ o) {
    extern __shared__ uint32_t su[];
    uint32_t* KV  = su + U_KV;
    uint32_t* QUb = su + U_QU;
    uint32_t* QVb = su + U_QV;
    uint32_t* PSb = su + U_PS;
    float*    S1  = (float*)(su + U_S1);
    float*    SC  = (float*)(su + U_SC);
    uint32_t* AT  = su + U_AT;
    const uint32_t smem_base = (uint32_t)__cvta_generic_to_shared(su);

    const int b  = blockIdx.z;
    const int h  = blockIdx.y;
    const int t0 = blockIdx.x * TQ;
    const int sb = t0 - WHALF;
    const int tid = threadIdx.x;
    const int warp = tid >> 5, lane = tid & 31;
    const int g = lane >> 2, t4 = lane & 3;

    // ---- phase 1: stage QU/QV, K, P
    for (int e = tid; e < TQ * 32; e += 256) {
        int qi = e >> 5, cu = e & 31;
        int tt = t0 + qi;
        float f0 = 0.f, f1 = 0.f;
        if (tt < TT) {
            uint32_t raw = *(const uint32_t*)(q + ((size_t)(b*TT+tt))*CC + h*DKK + cu*2);
            __nv_bfloat162 p = *(__nv_bfloat162*)&raw;
            f0 = __bfloat162float(p.x); f1 = __bfloat162float(p.y);
        }
        float u0 = pu[h*DKK + cu*2], u1 = pu[h*DKK + cu*2 + 1];
        float w0 = pv[h*DKK + cu*2], w1 = pv[h*DKK + cu*2 + 1];
        __nv_bfloat162 a, c;
        a.x = __float2bfloat16(f0 + u0); a.y = __float2bfloat16(f1 + u1);
        c.x = __float2bfloat16(f0 + w0); c.y = __float2bfloat16(f1 + w1);
        QUb[qi*36 + cu] = *(uint32_t*)&a;
        QVb[qi*36 + cu] = *(uint32_t*)&c;
    }
    for (int e = tid; e < 120 * 8; e += 256) {
        int si = e >> 3, c = e & 7;
        int s = sb + si;
        uint4 kk = make_uint4(0,0,0,0);
        if (s >= 0 && s < TT) kk = *(const uint4*)(k + ((size_t)(b*TT+s))*CC + h*DKK + c*8);
        *(uint4*)(KV + si*36 + c*4) = kk;
    }
    for (int e = tid; e < 104 * 8; e += 256) {
        int r = e >> 3, c = e & 7;
        uint4 pp = make_uint4(0,0,0,0);
        if (r < NR) pp = *(const uint4*)(pc + (size_t)r*CC + h*DKK + c*8);
        *(uint4*)(PSb + r*36 + c*4) = pp;
    }
    __syncthreads();

    // ---- phase 2: score GEMMs (A fragments hoisted)
    {
        uint4 af[4];
        #pragma unroll
        for (int ch = 0; ch < 4; ch++) {
            af[ch].x = QUb[g*36 + ch*8 + t4];
            af[ch].y = QUb[(g+8)*36 + ch*8 + t4];
            af[ch].z = QUb[g*36 + ch*8 + t4 + 4];
            af[ch].w = QUb[(g+8)*36 + ch*8 + t4 + 4];
        }
        for (int nt = warp; nt < 15; nt += 8) {
            float c[4] = {0.f, 0.f, 0.f, 0.f};
            #pragma unroll
            for (int ch = 0; ch < 4; ch++) {
                uint32_t b0 = KV[(nt*8+g)*36 + ch*8 + t4];
                uint32_t b1 = KV[(nt*8+g)*36 + ch*8 + t4 + 4];
                mma_bf16(c, af[ch], b0, b1);
            }
            *(float2*)(S1 + g*132 + nt*8 + 2*t4)     = make_float2(c[0], c[1]);
            *(float2*)(S1 + (g+8)*132 + nt*8 + 2*t4) = make_float2(c[2], c[3]);
        }
        #pragma unroll
        for (int ch = 0; ch < 4; ch++) {
            af[ch].x = QVb[g*36 + ch*8 + t4];
            af[ch].y = QVb[(g+8)*36 + ch*8 + t4];
            af[ch].z = QVb[g*36 + ch*8 + t4 + 4];
            af[ch].w = QVb[(g+8)*36 + ch*8 + t4 + 4];
        }
        for (int nt = warp; nt < 13; nt += 8) {
            float c[4] = {0.f, 0.f, 0.f, 0.f};
            #pragma unroll
            for (int ch = 0; ch < 4; ch++) {
                uint32_t b0 = PSb[(nt*8+g)*36 + ch*8 + t4];
                uint32_t b1 = PSb[(nt*8+g)*36 + ch*8 + t4 + 4];
                mma_bf16(c, af[ch], b0, b1);
            }
            *(float2*)(SC + g*104 + nt*8 + 2*t4)     = make_float2(c[0], c[1]);
            *(float2*)(SC + (g+8)*104 + nt*8 + 2*t4) = make_float2(c[2], c[3]);
        }
    }
    __syncthreads();

    // ---- phase 3a: combine+mask -> SC ; zero AT ; stage V (overwrites K)
    for (int e = tid; e < TQ * NR; e += 256) {
        int qi = e & 15, r = e >> 4;
        int tt = t0 + qi, s = tt + r - WHALF;
        float val = -1e30f;
        if (tt < TT && s >= 0 && s < TT)
            val = (S1[qi*132 + qi + r] + SC[qi*104 + r]) * 0.125f;
        SC[qi*104 + r] = val;
    }
    for (int e = tid; e < TQ * 68; e += 256) AT[e] = 0u;
    for (int e = tid; e < 128 * 8; e += 256) {
        int si = e >> 3, c = e & 7;
        int s = sb + si;
        uint4 vv = make_uint4(0,0,0,0);
        if (si < 120 && s >= 0 && s < TT)
            vv = *(const uint4*)(v + ((size_t)(b*TT+s))*CC + h*DKK + c*8);
        *(uint4*)(KV + si*36 + c*4) = vv;
    }
    __syncthreads();

    // ---- phase 3b: softmax (serial, 16 rows)
    if (tid < TQ) {
        float* srow = SC + tid * 104;
        float m = -1e30f;
        for (int r = 0; r < NR; r++) m = fmaxf(m, srow[r]);
        float sum = 0.f;
        for (int r = 0; r < NR; r++) { float ev = __expf(srow[r] - m); srow[r] = ev; sum += ev; }
        float inv = 1.f / sum;
        for (int r = 0; r < NR; r++) srow[r] *= inv;
    }
    __syncthreads();

    // ---- phase 3c: scatter bf16 weights into shifted AT
    for (int e = tid; e < TQ * NR; e += 256) {
        int qi = e & 15, r = e >> 4;
        ((__nv_bfloat16*)AT)[qi*136 + qi + r] = __float2bfloat16(SC[qi*104 + r]);
    }
    __syncthreads();

    // ---- phase 4: O = AT(16x128) @ V(128x64); warps 0-3, n16 each
    if (warp < 4) {
        int n0 = warp * 16;
        float c0[4] = {0.f,0.f,0.f,0.f};
        float c1[4] = {0.f,0.f,0.f,0.f};
        uint32_t vbase = smem_base + (U_KV + (lane & 15)*36 + (n0 >> 1) + (lane >> 4)*4) * 4;
        #pragma unroll
        for (int ch = 0; ch < 8; ch++) {
            uint4 a;
            a.x = AT[g*68 + ch*8 + t4];
            a.y = AT[(g+8)*68 + ch*8 + t4];
            a.z = AT[g*68 + ch*8 + t4 + 4];
            a.w = AT[(g+8)*68 + ch*8 + t4 + 4];
            uint4 bq;
            ldsm_x4_t(bq, vbase + (ch * 16 * 36) * 4);
            mma_bf16(c0, a, bq.x, bq.y);
            mma_bf16(c1, a, bq.z, bq.w);
        }
        int tg0 = t0 + g, tg1 = t0 + g + 8;
        if (tg0 < TT) {
            __nv_bfloat16* orow = o + ((size_t)(b*TT+tg0))*CC + h*DKK;
            __nv_bfloat162 p;
            p.x = __float2bfloat16(c0[0]); p.y = __float2bfloat16(c0[1]);
            *(__nv_bfloat162*)(orow + n0 + 2*t4) = p;
            p.x = __float2bfloat16(c1[0]); p.y = __float2bfloat16(c1[1]);
            *(__nv_bfloat162*)(orow + n0 + 8 + 2*t4) = p;
        }
        if (tg1 < TT) {
            __nv_bfloat16* orow = o + ((size_t)(b*TT+tg1))*CC + h*DKK;
            __nv_bfloat162 p;
            p.x = __float2bfloat16(c0[2]); p.y = __float2bfloat16(c0[3]);
            *(__nv_bfloat162*)(orow + n0 + 2*t4) = p;
            p.x = __float2bfloat16(c1[2]); p.y = __float2bfloat16(c1[3]);
            *(__nv_bfloat162*)(orow + n0 + 8 + 2*t4) = p;
        }
    }
}

// ---------------- driver ----------------
extern "C" void kernel_launch(void* const* d_in, const int* in_sizes, int n_in,
                              void* d_out, int out_size) {
    const float* x    = (const float*)d_in[0];
    const float* Wq   = (const float*)d_in[1];
    const float* bq   = (const float*)d_in[2];
    const float* Wk   = (const float*)d_in[3];
    const float* bk   = (const float*)d_in[4];
    const float* Wv   = (const float*)d_in[5];
    const float* bv   = (const float*)d_in[6];
    const float* Wo   = (const float*)d_in[7];
    const float* bo   = (const float*)d_in[8];
    const float* Wp   = (const float*)d_in[9];
    const float* pu   = (const float*)d_in[10];
    const float* pvv  = (const float*)d_in[11];
    const float* ln1g = (const float*)d_in[12];
    const float* ln1b = (const float*)d_in[13];
    const float* ln2g = (const float*)d_in[14];
    const float* ln2b = (const float*)d_in[15];
    const float* W1   = (const float*)d_in[16];
    const float* b1   = (const float*)d_in[17];
    const float* W2   = (const float*)d_in[18];
    const float* b2   = (const float*)d_in[19];
    // d_in[20] = att_mask: fixed band |i-j|>50, handled analytically.

    float* h;
    __nv_bfloat16 *ybf, *obf, *qb, *kb, *vb, *pcb, *pebf, *wbf;
    cudaGetSymbolAddress((void**)&h,    g_h);
    cudaGetSymbolAddress((void**)&ybf,  g_ybf);
    cudaGetSymbolAddress((void**)&obf,  g_obf);
    cudaGetSymbolAddress((void**)&qb,   g_qb);
    cudaGetSymbolAddress((void**)&kb,   g_kb);
    cudaGetSymbolAddress((void**)&vb,   g_vb);
    cudaGetSymbolAddress((void**)&pcb,  g_pcb);
    cudaGetSymbolAddress((void**)&pebf, g_pebf);
    cudaGetSymbolAddress((void**)&wbf,  g_wbf);

    cudaFuncSetAttribute(tgemm_kernel<1,1>, cudaFuncAttributeMaxDynamicSharedMemorySize, GEMM_SMEM);
    cudaFuncSetAttribute(tgemm_kernel<2,0>, cudaFuncAttributeMaxDynamicSharedMemorySize, GEMM_SMEM);
    cudaFuncSetAttribute(qkv_kernel,        cudaFuncAttributeMaxDynamicSharedMemorySize, GEMM_SMEM);
    cudaFuncSetAttribute(attn_kernel,       cudaFuncAttributeMaxDynamicSharedMemorySize, ATTN_SMEM_BYTES);

    setup_kernel<<<SETUP_BLKS, 256>>>(x, Wq, Wk, Wv, Wo, Wp, W1, W2);

    dim3 gBig(CC / 64, (BT + 127) / 128);        // (12, 32)
    dim3 gQKV(48, (BT + 127) / 128);             // (48, 32): qkv + fused Wp
    dim3 gAtt((TT + TQ - 1) / TQ, HH, BB);       // (63, 12, 4)

    for (int l = 0; l < LNUM; l++) {
        size_t wOff = (size_t)l * CC * CC;
        size_t bOff = (size_t)l * CC;

        ln_kernel<<<BT, 192>>>(h, ybf, ln1g + bOff, ln1b + bOff);
        qkv_kernel<<<gQKV, 256, GEMM_SMEM>>>(ybf,
            wbf + 0*WSZ + wOff, wbf + 1*WSZ + wOff, wbf + 2*WSZ + wOff,
            wbf + 4*WSZ + wOff,
            bq + bOff, bk + bOff, bv + bOff, qb, kb, vb, pebf, pcb);
        attn_kernel<<<gAtt, 256, ATTN_SMEM_BYTES>>>(qb, kb, vb, pcb, pu + bOff, pvv + bOff, obf);
        tgemm_kernel<2,0><<<gBig, 256, GEMM_SMEM>>>(obf, wbf + 3*WSZ + wOff,
            bo + bOff, h, h, BT, CC, CC);
        ln_kernel<<<BT, 192>>>(h, ybf, ln2g + bOff, ln2b + bOff);
        tgemm_kernel<1,1><<<gBig, 256, GEMM_SMEM>>>(ybf, wbf + 5*WSZ + wOff,
            b1 + bOff, nullptr, obf, BT, CC, CC);
        void* outp = (l == LNUM - 1) ? d_out : (void*)h;
        tgemm_kernel<2,0><<<gBig, 256, GEMM_SMEM>>>(obf, wbf + 6*WSZ + wOff,
            b2 + bOff, h, outp, BT, CC, CC);
    }
}

// round 16
// speedup vs baseline: 1.2353x; 1.0986x over previous
#include <cuda_runtime.h>
#include <cuda_bf16.h>
#include <math.h>
#include <stdint.h>

// ---------------- problem constants ----------------
#define LNUM 2
#define BB   4
#define TT   1000
#define CC   768
#define HH   12
#define DKK  64
#define WHALF 50         // band half-width (WIN//2)
#define NR   101         // relative positions actually reachable: -50..50
#define BT   (BB*TT)     // 4000 rows
#define WSZ  (LNUM*CC*CC)

// ---------------- device scratch (no allocs allowed) ----------------
__device__ float g_h[BT*CC];
__device__ __nv_bfloat16 g_ybf[BT*CC];        // LN output (GEMM A operand)
__device__ __nv_bfloat16 g_obf[BT*CC];        // attn out / gelu out (GEMM A operand)
__device__ __nv_bfloat16 g_qb[BT*CC];
__device__ __nv_bfloat16 g_kb[BT*CC];
__device__ __nv_bfloat16 g_vb[BT*CC];
__device__ __nv_bfloat16 g_pcb[NR*CC];        // pe @ Wp[l], bf16
__device__ __nv_bfloat16 g_pebf[NR*CC];       // positional table, bf16
__device__ __nv_bfloat16 g_wbf[7*WSZ];        // bf16 weights: Wq,Wk,Wv,Wo,Wp,W1,W2

// ---------------- fused setup: f2b (all 7 weights) + init_h + pe ----------------
#define F2B_BLKS  (7 * (WSZ / 4) / 256)            // 8064
#define INIT_BLKS ((BT * CC / 4) / 256)            // 3000
#define PE_BLKS   ((NR * (CC/2) + 255) / 256)      // 152
#define SETUP_BLKS (F2B_BLKS + INIT_BLKS + PE_BLKS)

__global__ void setup_kernel(const float* __restrict__ x,
                             const float* __restrict__ s0, const float* __restrict__ s1,
                             const float* __restrict__ s2, const float* __restrict__ s3,
                             const float* __restrict__ s4, const float* __restrict__ s5,
                             const float* __restrict__ s6) {
    int bx = blockIdx.x;
    if (bx < F2B_BLKS) {
        const int per = WSZ / 4;
        int i4 = bx * 256 + threadIdx.x;
        int t = i4 / per;
        int off = i4 - t * per;
        const float* src = (t == 0) ? s0 : (t == 1) ? s1 : (t == 2) ? s2 :
                           (t == 3) ? s3 : (t == 4) ? s4 : (t == 5) ? s5 : s6;
        float4 vv = ((const float4*)src)[off];
        __nv_bfloat162 a, b;
        a.x = __float2bfloat16(vv.x); a.y = __float2bfloat16(vv.y);
        b.x = __float2bfloat16(vv.z); b.y = __float2bfloat16(vv.w);
        __nv_bfloat162* dst = (__nv_bfloat162*)(g_wbf + (size_t)t * WSZ);
        dst[off * 2]     = a;
        dst[off * 2 + 1] = b;
    } else if (bx < F2B_BLKS + INIT_BLKS) {
        int i4 = (bx - F2B_BLKS) * 256 + threadIdx.x;
        float4 vv = ((const float4*)x)[i4];
        const float sc = 27.712812921102035f;  // sqrt(768)
        ((float4*)g_h)[i4] = make_float4(vv.x*sc, vv.y*sc, vv.z*sc, vv.w*sc);
    } else {
        int i = (bx - F2B_BLKS - INIT_BLKS) * 256 + threadIdx.x;
        if (i < NR*(CC/2)) {
            int r = i / (CC/2);
            int j = i % (CC/2);
            float div = expf(-(float)(2*j) * (9.210340371976184f / (float)CC));
            float ang = (float)(WHALF - r) * div;
            g_pebf[r*CC + 2*j]     = __float2bfloat16(sinf(ang));
            g_pebf[r*CC + 2*j + 1] = __float2bfloat16(cosf(ang));
        }
    }
}

// LayerNorm: fp32 in, bf16 out. 1 row/block, 192 threads (all active).
__global__ void __launch_bounds__(192)
ln_kernel(const float* __restrict__ in, __nv_bfloat16* __restrict__ out,
          const float* __restrict__ g, const float* __restrict__ b) {
    const int row = blockIdx.x;
    const int tid = threadIdx.x;
    const float4* xr = (const float4*)(in + (size_t)row * CC);
    float4 vv = xr[tid];
    float s  = vv.x + vv.y + vv.z + vv.w;
    float s2 = vv.x*vv.x + vv.y*vv.y + vv.z*vv.z + vv.w*vv.w;
    __shared__ float sh[16];
    #pragma unroll
    for (int o = 16; o; o >>= 1) {
        s  += __shfl_xor_sync(0xffffffffu, s,  o);
        s2 += __shfl_xor_sync(0xffffffffu, s2, o);
    }
    int w = tid >> 5;
    if ((tid & 31) == 0) { sh[w] = s; sh[8 + w] = s2; }
    __syncthreads();
    s = 0.f; s2 = 0.f;
    #pragma unroll
    for (int i = 0; i < 6; i++) { s += sh[i]; s2 += sh[8 + i]; }
    float mean = s * (1.f / CC);
    float var  = s2 * (1.f / CC) - mean * mean;
    float rstd = rsqrtf(var + 1e-5f);
    float4 g4 = ((const float4*)g)[tid];
    float4 b4 = ((const float4*)b)[tid];
    __nv_bfloat162 p0, p1;
    p0.x = __float2bfloat16((vv.x - mean) * rstd * g4.x + b4.x);
    p0.y = __float2bfloat16((vv.y - mean) * rstd * g4.y + b4.y);
    p1.x = __float2bfloat16((vv.z - mean) * rstd * g4.z + b4.z);
    p1.y = __float2bfloat16((vv.w - mean) * rstd * g4.w + b4.w);
    uint2 u;
    u.x = *(uint32_t*)&p0;
    u.y = *(uint32_t*)&p1;
    ((uint2*)(out + (size_t)row * CC))[tid] = u;
}

// ---------------- mma / ldmatrix / cp.async helpers ----------------
__device__ __forceinline__ void mma_bf16(float c[4], const uint4& a, uint32_t b0, uint32_t b1) {
    asm volatile(
        "mma.sync.aligned.m16n8k16.row.col.f32.bf16.bf16.f32 "
        "{%0,%1,%2,%3}, {%4,%5,%6,%7}, {%8,%9}, {%0,%1,%2,%3};"
        : "+f"(c[0]), "+f"(c[1]), "+f"(c[2]), "+f"(c[3])
        : "r"(a.x), "r"(a.y), "r"(a.z), "r"(a.w), "r"(b0), "r"(b1));
}
__device__ __forceinline__ void ldsm_x4(uint4& d, uint32_t addr) {
    asm volatile("ldmatrix.sync.aligned.m8n8.x4.shared.b16 {%0,%1,%2,%3}, [%4];"
                 : "=r"(d.x), "=r"(d.y), "=r"(d.z), "=r"(d.w) : "r"(addr));
}
__device__ __forceinline__ void ldsm_x4_t(uint4& d, uint32_t addr) {
    asm volatile("ldmatrix.sync.aligned.m8n8.x4.trans.shared.b16 {%0,%1,%2,%3}, [%4];"
                 : "=r"(d.x), "=r"(d.y), "=r"(d.z), "=r"(d.w) : "r"(addr));
}
__device__ __forceinline__ void cp16(uint32_t dst, const void* src, int srcsize) {
    asm volatile("cp.async.cg.shared.global [%0], [%1], 16, %2;\n"
                 :: "r"(dst), "l"(src), "r"(srcsize));
}
__device__ __forceinline__ void cp_commit() {
    asm volatile("cp.async.commit_group;\n");
}
template<int N> __device__ __forceinline__ void cp_wait() {
    asm volatile("cp.async.wait_group %0;\n" :: "n"(N));
}

__device__ __forceinline__ float gelu_f(float x) {
    float x3 = x * x * x;
    return 0.5f * x * (1.f + tanhf(0.7978845608028654f * (x + 0.044715f * x3)));
}

// ---------------- bf16 tensor-core GEMM, 3-stage cp.async (R12 proven) ----------------
#define AST2 20
#define BST2 36
#define STG_A (128*AST2)   // 2560 u32
#define STG_B (32*BST2)    // 1152 u32
#define GEMM_SMEM (3*(STG_A+STG_B)*4)   // 44544 bytes

template<int EPI, int OUTBF>
__device__ __forceinline__ void gemm_body(
        const __nv_bfloat16* __restrict__ A, const __nv_bfloat16* __restrict__ Bm,
        const float* __restrict__ bias, const float* __restrict__ resid,
        void* __restrict__ Cm, int M, int N, int K, int row0, int col0) {
    extern __shared__ uint32_t smu[];
    const uint32_t smem_base = (uint32_t)__cvta_generic_to_shared(smu);

    const int tid  = threadIdx.x;
    const int warp = tid >> 5;
    const int lane = tid & 31;
    const int g    = lane >> 2;
    const int t    = lane & 3;
    const int wr   = warp >> 1;
    const int wc   = warp & 1;

    float acc[2][4][4];
    #pragma unroll
    for (int i = 0; i < 2; i++)
        #pragma unroll
        for (int j = 0; j < 4; j++)
            #pragma unroll
            for (int r = 0; r < 4; r++) acc[i][j][r] = 0.f;

    const int a_r = tid >> 2, a_c = tid & 3;
    const int b_r = tid >> 3, b_c = tid & 7;

#define LOADS(s_) do {                                                              \
        const int k0_ = (s_) * 32;                                                  \
        uint32_t* Ab_ = smu + ((s_) % 3) * (STG_A + STG_B);                         \
        uint32_t* Bb_ = Ab_ + STG_A;                                                \
        _Pragma("unroll")                                                           \
        for (int i_ = 0; i_ < 2; i_++) {                                            \
            int r_ = a_r + i_ * 64;                                                 \
            int gr_ = row0 + r_;                                                    \
            int ok_ = (gr_ < M) ? 16 : 0;                                           \
            const __nv_bfloat16* src_ = A + (size_t)(ok_ ? gr_ : 0) * K + k0_ + a_c * 8; \
            cp16((uint32_t)__cvta_generic_to_shared(Ab_ + r_ * AST2 + a_c * 4), src_, ok_); \
        }                                                                           \
        {                                                                           \
            const __nv_bfloat16* src_ = Bm + (size_t)(k0_ + b_r) * N + col0 + b_c * 8;   \
            cp16((uint32_t)__cvta_generic_to_shared(Bb_ + b_r * BST2 + b_c * 4), src_, 16); \
        }                                                                           \
    } while (0)

    const int steps = K >> 5;
    LOADS(0); cp_commit();
    LOADS(1); cp_commit();

    const int a_lane_off = (lane & 15) * AST2 + (lane >> 4) * 4;
    const int b_lane_off = (lane & 15) * BST2 + wc * 16 + (lane >> 4) * 4;

    for (int s = 0; s < steps; s++) {
        cp_wait<1>();
        __syncthreads();
        if (s + 2 < steps) LOADS(s + 2);
        cp_commit();

        const uint32_t bufo = (uint32_t)((s % 3) * (STG_A + STG_B));
        const uint32_t abase = smem_base + (bufo + wr * 32 * AST2 + a_lane_off) * 4;
        const uint32_t bbase = smem_base + (bufo + STG_A + b_lane_off) * 4;

        #pragma unroll
        for (int ch = 0; ch < 2; ch++) {
            uint4 af[2];
            #pragma unroll
            for (int i = 0; i < 2; i++)
                ldsm_x4(af[i], abase + (i * 16 * AST2 + ch * 8) * 4);
            uint4 bq[2];
            #pragma unroll
            for (int jj = 0; jj < 2; jj++)
                ldsm_x4_t(bq[jj], bbase + (ch * 16 * BST2 + jj * 8) * 4);
            #pragma unroll
            for (int i = 0; i < 2; i++) {
                mma_bf16(acc[i][0], af[i], bq[0].x, bq[0].y);
                mma_bf16(acc[i][1], af[i], bq[0].z, bq[0].w);
                mma_bf16(acc[i][2], af[i], bq[1].x, bq[1].y);
                mma_bf16(acc[i][3], af[i], bq[1].z, bq[1].w);
            }
        }
    }
#undef LOADS

    __syncthreads();

    #pragma unroll
    for (int i = 0; i < 2; i++) {
        int rbase = row0 + wr * 32 + i * 16 + g;
        #pragma unroll
        for (int j = 0; j < 4; j++) {
            int col = col0 + wc * 32 + j * 8 + t * 2;
            float bx = 0.f, by = 0.f;
            if (bias) { bx = bias[col]; by = bias[col + 1]; }
            #pragma unroll
            for (int hh = 0; hh < 2; hh++) {
                int row = rbase + hh * 8;
                if (row < M) {
                    float c0 = acc[i][j][hh * 2 + 0] + bx;
                    float c1 = acc[i][j][hh * 2 + 1] + by;
                    if (EPI == 1) { c0 = gelu_f(c0); c1 = gelu_f(c1); }
                    if (EPI == 2) {
                        float2 rv = *(const float2*)(resid + (size_t)row * N + col);
                        c0 += rv.x; c1 += rv.y;
                    }
                    if (OUTBF) {
                        __nv_bfloat162 p;
                        p.x = __float2bfloat16(c0);
                        p.y = __float2bfloat16(c1);
                        *(__nv_bfloat162*)((__nv_bfloat16*)Cm + (size_t)row * N + col) = p;
                    } else {
                        *(float2*)((float*)Cm + (size_t)row * N + col) = make_float2(c0, c1);
                    }
                }
            }
        }
    }
}

template<int EPI, int OUTBF>
__global__ void __launch_bounds__(256)
tgemm_kernel(const __nv_bfloat16* __restrict__ A, const __nv_bfloat16* __restrict__ Bm,
             const float* __restrict__ bias, const float* __restrict__ resid,
             void* __restrict__ Cm, int M, int N, int K) {
    gemm_body<EPI, OUTBF>(A, Bm, bias, resid, Cm, M, N, K,
                          blockIdx.y * 128, blockIdx.x * 64);
}

// fused QKV + Wp: blockIdx.x in [0,48). [0,36): sel=x/12 picks {q,k,v};
// [36,48): the tiny pe@Wp GEMM (M=101) on blockIdx.y==0 only.
__global__ void __launch_bounds__(256)
qkv_kernel(const __nv_bfloat16* __restrict__ A,
           const __nv_bfloat16* __restrict__ Bq, const __nv_bfloat16* __restrict__ Bk,
           const __nv_bfloat16* __restrict__ Bv, const __nv_bfloat16* __restrict__ Bp,
           const float* __restrict__ bq, const float* __restrict__ bk,
           const float* __restrict__ bv,
           __nv_bfloat16* __restrict__ Cq, __nv_bfloat16* __restrict__ Ck,
           __nv_bfloat16* __restrict__ Cv,
           const __nv_bfloat16* __restrict__ pe, __nv_bfloat16* __restrict__ Cp) {
    int xx = blockIdx.x;
    if (xx < 36) {
        int sel = xx / 12;
        int colblk = xx % 12;
        const __nv_bfloat16* Bm = (sel == 0) ? Bq : (sel == 1) ? Bk : Bv;
        const float* bias       = (sel == 0) ? bq : (sel == 1) ? bk : bv;
        __nv_bfloat16* Cm       = (sel == 0) ? Cq : (sel == 1) ? Ck : Cv;
        gemm_body<0, 1>(A, Bm, bias, nullptr, Cm, BT, CC, CC,
                        blockIdx.y * 128, colblk * 64);
    } else {
        if (blockIdx.y != 0) return;
        int colblk = xx - 36;
        gemm_body<0, 1>(pe, Bp, nullptr, nullptr, Cp, NR, CC, CC,
                        0, colblk * 64);
    }
}

// ---------------- banded rel-pos attention (bf16 tensor-core, TQ=16) ----------------
// Changes vs R14: (1) warp-parallel softmax fused with bf16 scatter into AT;
// (2) AT zeroing in phase 1; (3) S1 stride 132 -> 124 (smem 56960B -> 4 blk/SM).
#define TQ 16

#define U_KV 0            // 128 rows x 36 u32 (K, then V)
#define U_QU 4608         // 16 x 36
#define U_QV 5184         // 16 x 36
#define U_PS 5760         // 104 x 36
#define U_S1 9504         // fp32 16 x 124
#define U_SC 11488        // fp32 16 x 104
#define U_AT 13152        // bf16 16 x 68 u32 (= 136 bf16 cols)
#define ATTN_U32 14240
#define ATTN_SMEM_BYTES (ATTN_U32*4)   // 56960

__global__ void __launch_bounds__(256)
attn_kernel(const __nv_bfloat16* __restrict__ q, const __nv_bfloat16* __restrict__ k,
            const __nv_bfloat16* __restrict__ v, const __nv_bfloat16* __restrict__ pc,
            const float* __restrict__ pu, const float* __restrict__ pv,
            __nv_bfloat16* __restrict__ o) {
    extern __shared__ uint32_t su[];
    uint32_t* KV  = su + U_KV;
    uint32_t* QUb = su + U_QU;
    uint32_t* QVb = su + U_QV;
    uint32_t* PSb = su + U_PS;
    float*    S1  = (float*)(su + U_S1);
    float*    SC  = (float*)(su + U_SC);
    uint32_t* AT  = su + U_AT;
    const uint32_t smem_base = (uint32_t)__cvta_generic_to_shared(su);

    const int b  = blockIdx.z;
    const int h  = blockIdx.y;
    const int t0 = blockIdx.x * TQ;
    const int sb = t0 - WHALF;
    const int tid = threadIdx.x;
    const int warp = tid >> 5, lane = tid & 31;
    const int g = lane >> 2, t4 = lane & 3;

    // ---- phase 1: stage QU/QV, K, P ; zero AT
    for (int e = tid; e < TQ * 32; e += 256) {
        int qi = e >> 5, cu = e & 31;
        int tt = t0 + qi;
        float f0 = 0.f, f1 = 0.f;
        if (tt < TT) {
            uint32_t raw = *(const uint32_t*)(q + ((size_t)(b*TT+tt))*CC + h*DKK + cu*2);
            __nv_bfloat162 p = *(__nv_bfloat162*)&raw;
            f0 = __bfloat162float(p.x); f1 = __bfloat162float(p.y);
        }
        float u0 = pu[h*DKK + cu*2], u1 = pu[h*DKK + cu*2 + 1];
        float w0 = pv[h*DKK + cu*2], w1 = pv[h*DKK + cu*2 + 1];
        __nv_bfloat162 a, c;
        a.x = __float2bfloat16(f0 + u0); a.y = __float2bfloat16(f1 + u1);
        c.x = __float2bfloat16(f0 + w0); c.y = __float2bfloat16(f1 + w1);
        QUb[qi*36 + cu] = *(uint32_t*)&a;
        QVb[qi*36 + cu] = *(uint32_t*)&c;
    }
    for (int e = tid; e < 120 * 8; e += 256) {
        int si = e >> 3, c = e & 7;
        int s = sb + si;
        uint4 kk = make_uint4(0,0,0,0);
        if (s >= 0 && s < TT) kk = *(const uint4*)(k + ((size_t)(b*TT+s))*CC + h*DKK + c*8);
        *(uint4*)(KV + si*36 + c*4) = kk;
    }
    for (int e = tid; e < 104 * 8; e += 256) {
        int r = e >> 3, c = e & 7;
        uint4 pp = make_uint4(0,0,0,0);
        if (r < NR) pp = *(const uint4*)(pc + (size_t)r*CC + h*DKK + c*8);
        *(uint4*)(PSb + r*36 + c*4) = pp;
    }
    for (int e = tid; e < TQ * 68; e += 256) AT[e] = 0u;
    __syncthreads();

    // ---- phase 2: score GEMMs (A fragments hoisted)
    {
        uint4 af[4];
        #pragma unroll
        for (int ch = 0; ch < 4; ch++) {
            af[ch].x = QUb[g*36 + ch*8 + t4];
            af[ch].y = QUb[(g+8)*36 + ch*8 + t4];
            af[ch].z = QUb[g*36 + ch*8 + t4 + 4];
            af[ch].w = QUb[(g+8)*36 + ch*8 + t4 + 4];
        }
        for (int nt = warp; nt < 15; nt += 8) {
            float c[4] = {0.f, 0.f, 0.f, 0.f};
            #pragma unroll
            for (int ch = 0; ch < 4; ch++) {
                uint32_t b0 = KV[(nt*8+g)*36 + ch*8 + t4];
                uint32_t b1 = KV[(nt*8+g)*36 + ch*8 + t4 + 4];
                mma_bf16(c, af[ch], b0, b1);
            }
            *(float2*)(S1 + g*124 + nt*8 + 2*t4)     = make_float2(c[0], c[1]);
            *(float2*)(S1 + (g+8)*124 + nt*8 + 2*t4) = make_float2(c[2], c[3]);
        }
        #pragma unroll
        for (int ch = 0; ch < 4; ch++) {
            af[ch].x = QVb[g*36 + ch*8 + t4];
            af[ch].y = QVb[(g+8)*36 + ch*8 + t4];
            af[ch].z = QVb[g*36 + ch*8 + t4 + 4];
            af[ch].w = QVb[(g+8)*36 + ch*8 + t4 + 4];
        }
        for (int nt = warp; nt < 13; nt += 8) {
            float c[4] = {0.f, 0.f, 0.f, 0.f};
            #pragma unroll
            for (int ch = 0; ch < 4; ch++) {
                uint32_t b0 = PSb[(nt*8+g)*36 + ch*8 + t4];
                uint32_t b1 = PSb[(nt*8+g)*36 + ch*8 + t4 + 4];
                mma_bf16(c, af[ch], b0, b1);
            }
            *(float2*)(SC + g*104 + nt*8 + 2*t4)     = make_float2(c[0], c[1]);
            *(float2*)(SC + (g+8)*104 + nt*8 + 2*t4) = make_float2(c[2], c[3]);
        }
    }
    __syncthreads();

    // ---- phase 3a: combine+mask -> SC ; stage V (overwrites K)
    for (int e = tid; e < TQ * NR; e += 256) {
        int qi = e & 15, r = e >> 4;
        int tt = t0 + qi, s = tt + r - WHALF;
        float val = -1e30f;
        if (tt < TT && s >= 0 && s < TT)
            val = (S1[qi*124 + qi + r] + SC[qi*104 + r]) * 0.125f;
        SC[qi*104 + r] = val;
    }
    for (int e = tid; e < 128 * 8; e += 256) {
        int si = e >> 3, c = e & 7;
        int s = sb + si;
        uint4 vv = make_uint4(0,0,0,0);
        if (si < 120 && s >= 0 && s < TT)
            vv = *(const uint4*)(v + ((size_t)(b*TT+s))*CC + h*DKK + c*8);
        *(uint4*)(KV + si*36 + c*4) = vv;
    }
    __syncthreads();

    // ---- phase 3b: warp-parallel softmax fused with bf16 scatter into AT.
    // Warp w owns rows 2w, 2w+1. Lane holds scores r = lane, +32, +64, +96.
    {
        #pragma unroll
        for (int rr = 0; rr < 2; rr++) {
            int qi = warp * 2 + rr;
            const float* srow = SC + qi * 104;
            float v0 = srow[lane];
            float v1 = srow[lane + 32];
            float v2 = srow[lane + 64];
            float v3 = (lane + 96 < NR) ? srow[lane + 96] : -1e30f;
            float m = fmaxf(fmaxf(v0, v1), fmaxf(v2, v3));
            #pragma unroll
            for (int oo = 16; oo; oo >>= 1)
                m = fmaxf(m, __shfl_xor_sync(0xffffffffu, m, oo));
            float e0 = __expf(v0 - m);
            float e1 = __expf(v1 - m);
            float e2 = __expf(v2 - m);
            float e3 = (lane + 96 < NR) ? __expf(v3 - m) : 0.f;
            float sum = e0 + e1 + e2 + e3;
            #pragma unroll
            for (int oo = 16; oo; oo >>= 1)
                sum += __shfl_xor_sync(0xffffffffu, sum, oo);
            float inv = 1.f / sum;
            __nv_bfloat16* at = (__nv_bfloat16*)AT + qi * 136 + qi;
            at[lane]      = __float2bfloat16(e0 * inv);
            at[lane + 32] = __float2bfloat16(e1 * inv);
            at[lane + 64] = __float2bfloat16(e2 * inv);
            if (lane + 96 < NR) at[lane + 96] = __float2bfloat16(e3 * inv);
        }
    }
    __syncthreads();

    // ---- phase 4: O = AT(16x128) @ V(128x64); warps 0-3, n16 each
    if (warp < 4) {
        int n0 = warp * 16;
        float c0[4] = {0.f,0.f,0.f,0.f};
        float c1[4] = {0.f,0.f,0.f,0.f};
        uint32_t vbase = smem_base + (U_KV + (lane & 15)*36 + (n0 >> 1) + (lane >> 4)*4) * 4;
        #pragma unroll
        for (int ch = 0; ch < 8; ch++) {
            uint4 a;
            a.x = AT[g*68 + ch*8 + t4];
            a.y = AT[(g+8)*68 + ch*8 + t4];
            a.z = AT[g*68 + ch*8 + t4 + 4];
            a.w = AT[(g+8)*68 + ch*8 + t4 + 4];
            uint4 bq;
            ldsm_x4_t(bq, vbase + (ch * 16 * 36) * 4);
            mma_bf16(c0, a, bq.x, bq.y);
            mma_bf16(c1, a, bq.z, bq.w);
        }
        int tg0 = t0 + g, tg1 = t0 + g + 8;
        if (tg0 < TT) {
            __nv_bfloat16* orow = o + ((size_t)(b*TT+tg0))*CC + h*DKK;
            __nv_bfloat162 p;
            p.x = __float2bfloat16(c0[0]); p.y = __float2bfloat16(c0[1]);
            *(__nv_bfloat162*)(orow + n0 + 2*t4) = p;
            p.x = __float2bfloat16(c1[0]); p.y = __float2bfloat16(c1[1]);
            *(__nv_bfloat162*)(orow + n0 + 8 + 2*t4) = p;
        }
        if (tg1 < TT) {
            __nv_bfloat16* orow = o + ((size_t)(b*TT+tg1))*CC + h*DKK;
            __nv_bfloat162 p;
            p.x = __float2bfloat16(c0[2]); p.y = __float2bfloat16(c0[3]);
            *(__nv_bfloat162*)(orow + n0 + 2*t4) = p;
            p.x = __float2bfloat16(c1[2]); p.y = __float2bfloat16(c1[3]);
            *(__nv_bfloat162*)(orow + n0 + 8 + 2*t4) = p;
        }
    }
}

// ---------------- driver ----------------
extern "C" void kernel_launch(void* const* d_in, const int* in_sizes, int n_in,
                              void* d_out, int out_size) {
    const float* x    = (const float*)d_in[0];
    const float* Wq   = (const float*)d_in[1];
    const float* bq   = (const float*)d_in[2];
    const float* Wk   = (const float*)d_in[3];
    const float* bk   = (const float*)d_in[4];
    const float* Wv   = (const float*)d_in[5];
    const float* bv   = (const float*)d_in[6];
    const float* Wo   = (const float*)d_in[7];
    const float* bo   = (const float*)d_in[8];
    const float* Wp   = (const float*)d_in[9];
    const float* pu   = (const float*)d_in[10];
    const float* pvv  = (const float*)d_in[11];
    const float* ln1g = (const float*)d_in[12];
    const float* ln1b = (const float*)d_in[13];
    const float* ln2g = (const float*)d_in[14];
    const float* ln2b = (const float*)d_in[15];
    const float* W1   = (const float*)d_in[16];
    const float* b1   = (const float*)d_in[17];
    const float* W2   = (const float*)d_in[18];
    const float* b2   = (const float*)d_in[19];
    // d_in[20] = att_mask: fixed band |i-j|>50, handled analytically.

    float* h;
    __nv_bfloat16 *ybf, *obf, *qb, *kb, *vb, *pcb, *pebf, *wbf;
    cudaGetSymbolAddress((void**)&h,    g_h);
    cudaGetSymbolAddress((void**)&ybf,  g_ybf);
    cudaGetSymbolAddress((void**)&obf,  g_obf);
    cudaGetSymbolAddress((void**)&qb,   g_qb);
    cudaGetSymbolAddress((void**)&kb,   g_kb);
    cudaGetSymbolAddress((void**)&vb,   g_vb);
    cudaGetSymbolAddress((void**)&pcb,  g_pcb);
    cudaGetSymbolAddress((void**)&pebf, g_pebf);
    cudaGetSymbolAddress((void**)&wbf,  g_wbf);

    cudaFuncSetAttribute(tgemm_kernel<1,1>, cudaFuncAttributeMaxDynamicSharedMemorySize, GEMM_SMEM);
    cudaFuncSetAttribute(tgemm_kernel<2,0>, cudaFuncAttributeMaxDynamicSharedMemorySize, GEMM_SMEM);
    cudaFuncSetAttribute(qkv_kernel,        cudaFuncAttributeMaxDynamicSharedMemorySize, GEMM_SMEM);
    cudaFuncSetAttribute(attn_kernel,       cudaFuncAttributeMaxDynamicSharedMemorySize, ATTN_SMEM_BYTES);

    setup_kernel<<<SETUP_BLKS, 256>>>(x, Wq, Wk, Wv, Wo, Wp, W1, W2);

    dim3 gBig(CC / 64, (BT + 127) / 128);        // (12, 32)
    dim3 gQKV(48, (BT + 127) / 128);             // (48, 32): qkv + fused Wp
    dim3 gAtt((TT + TQ - 1) / TQ, HH, BB);       // (63, 12, 4)

    for (int l = 0; l < LNUM; l++) {
        size_t wOff = (size_t)l * CC * CC;
        size_t bOff = (size_t)l * CC;

        ln_kernel<<<BT, 192>>>(h, ybf, ln1g + bOff, ln1b + bOff);
        qkv_kernel<<<gQKV, 256, GEMM_SMEM>>>(ybf,
            wbf + 0*WSZ + wOff, wbf + 1*WSZ + wOff, wbf + 2*WSZ + wOff,
            wbf + 4*WSZ + wOff,
            bq + bOff, bk + bOff, bv + bOff, qb, kb, vb, pebf, pcb);
        attn_kernel<<<gAtt, 256, ATTN_SMEM_BYTES>>>(qb, kb, vb, pcb, pu + bOff, pvv + bOff, obf);
        tgemm_kernel<2,0><<<gBig, 256, GEMM_SMEM>>>(obf, wbf + 3*WSZ + wOff,
            bo + bOff, h, h, BT, CC, CC);
        ln_kernel<<<BT, 192>>>(h, ybf, ln2g + bOff, ln2b + bOff);
        tgemm_kernel<1,1><<<gBig, 256, GEMM_SMEM>>>(ybf, wbf + 5*WSZ + wOff,
            b1 + bOff, nullptr, obf, BT, CC, CC);
        void* outp = (l == LNUM - 1) ? d_out : (void*)h;
        tgemm_kernel<2,0><<<gBig, 256, GEMM_SMEM>>>(obf, wbf + 6*WSZ + wOff,
            b2 + bOff, h, outp, BT, CC, CC);
    }
}

// round 17
// speedup vs baseline: 1.2463x; 1.0089x over previous
#include <cuda_runtime.h>
#include <cuda_bf16.h>
#include <math.h>
#include <stdint.h>

// ---------------- problem constants ----------------
#define LNUM 2
#define BB   4
#define TT   1000
#define CC   768
#define HH   12
#define DKK  64
#define WHALF 50         // band half-width (WIN//2)
#define NR   101         // relative positions actually reachable: -50..50
#define BT   (BB*TT)     // 4000 rows
#define WSZ  (LNUM*CC*CC)

// ---------------- device scratch (no allocs allowed) ----------------
__device__ float g_h[BT*CC];
__device__ __nv_bfloat16 g_ybf[BT*CC];        // LN output (GEMM A operand)
__device__ __nv_bfloat16 g_obf[BT*CC];        // attn out / gelu out (GEMM A operand)
__device__ __nv_bfloat16 g_qb[BT*CC];
__device__ __nv_bfloat16 g_kb[BT*CC];
__device__ __nv_bfloat16 g_vb[BT*CC];
__device__ __nv_bfloat16 g_pcb[NR*CC];        // pe @ Wp[l], bf16
__device__ __nv_bfloat16 g_pebf[NR*CC];       // positional table, bf16
__device__ __nv_bfloat16 g_wbf[7*WSZ];        // bf16 weights: Wq,Wk,Wv,Wo,Wp,W1,W2

// ---------------- fused setup: f2b (all 7 weights) + init_h + pe ----------------
#define F2B_BLKS  (7 * (WSZ / 4) / 256)            // 8064
#define INIT_BLKS ((BT * CC / 4) / 256)            // 3000
#define PE_BLKS   ((NR * (CC/2) + 255) / 256)      // 152
#define SETUP_BLKS (F2B_BLKS + INIT_BLKS + PE_BLKS)

__global__ void setup_kernel(const float* __restrict__ x,
                             const float* __restrict__ s0, const float* __restrict__ s1,
                             const float* __restrict__ s2, const float* __restrict__ s3,
                             const float* __restrict__ s4, const float* __restrict__ s5,
                             const float* __restrict__ s6) {
    int bx = blockIdx.x;
    if (bx < F2B_BLKS) {
        const int per = WSZ / 4;
        int i4 = bx * 256 + threadIdx.x;
        int t = i4 / per;
        int off = i4 - t * per;
        const float* src = (t == 0) ? s0 : (t == 1) ? s1 : (t == 2) ? s2 :
                           (t == 3) ? s3 : (t == 4) ? s4 : (t == 5) ? s5 : s6;
        float4 vv = ((const float4*)src)[off];
        __nv_bfloat162 a, b;
        a.x = __float2bfloat16(vv.x); a.y = __float2bfloat16(vv.y);
        b.x = __float2bfloat16(vv.z); b.y = __float2bfloat16(vv.w);
        __nv_bfloat162* dst = (__nv_bfloat162*)(g_wbf + (size_t)t * WSZ);
        dst[off * 2]     = a;
        dst[off * 2 + 1] = b;
    } else if (bx < F2B_BLKS + INIT_BLKS) {
        int i4 = (bx - F2B_BLKS) * 256 + threadIdx.x;
        float4 vv = ((const float4*)x)[i4];
        const float sc = 27.712812921102035f;  // sqrt(768)
        ((float4*)g_h)[i4] = make_float4(vv.x*sc, vv.y*sc, vv.z*sc, vv.w*sc);
    } else {
        int i = (bx - F2B_BLKS - INIT_BLKS) * 256 + threadIdx.x;
        if (i < NR*(CC/2)) {
            int r = i / (CC/2);
            int j = i % (CC/2);
            float div = expf(-(float)(2*j) * (9.210340371976184f / (float)CC));
            float ang = (float)(WHALF - r) * div;
            g_pebf[r*CC + 2*j]     = __float2bfloat16(sinf(ang));
            g_pebf[r*CC + 2*j + 1] = __float2bfloat16(cosf(ang));
        }
    }
}

// LayerNorm: fp32 in, bf16 out. 1 row/block, 192 threads (all active).
__global__ void __launch_bounds__(192)
ln_kernel(const float* __restrict__ in, __nv_bfloat16* __restrict__ out,
          const float* __restrict__ g, const float* __restrict__ b) {
    const int row = blockIdx.x;
    const int tid = threadIdx.x;
    const float4* xr = (const float4*)(in + (size_t)row * CC);
    float4 vv = xr[tid];
    float s  = vv.x + vv.y + vv.z + vv.w;
    float s2 = vv.x*vv.x + vv.y*vv.y + vv.z*vv.z + vv.w*vv.w;
    __shared__ float sh[16];
    #pragma unroll
    for (int o = 16; o; o >>= 1) {
        s  += __shfl_xor_sync(0xffffffffu, s,  o);
        s2 += __shfl_xor_sync(0xffffffffu, s2, o);
    }
    int w = tid >> 5;
    if ((tid & 31) == 0) { sh[w] = s; sh[8 + w] = s2; }
    __syncthreads();
    s = 0.f; s2 = 0.f;
    #pragma unroll
    for (int i = 0; i < 6; i++) { s += sh[i]; s2 += sh[8 + i]; }
    float mean = s * (1.f / CC);
    float var  = s2 * (1.f / CC) - mean * mean;
    float rstd = rsqrtf(var + 1e-5f);
    float4 g4 = ((const float4*)g)[tid];
    float4 b4 = ((const float4*)b)[tid];
    __nv_bfloat162 p0, p1;
    p0.x = __float2bfloat16((vv.x - mean) * rstd * g4.x + b4.x);
    p0.y = __float2bfloat16((vv.y - mean) * rstd * g4.y + b4.y);
    p1.x = __float2bfloat16((vv.z - mean) * rstd * g4.z + b4.z);
    p1.y = __float2bfloat16((vv.w - mean) * rstd * g4.w + b4.w);
    uint2 u;
    u.x = *(uint32_t*)&p0;
    u.y = *(uint32_t*)&p1;
    ((uint2*)(out + (size_t)row * CC))[tid] = u;
}

// ---------------- mma / ldmatrix / cp.async helpers ----------------
__device__ __forceinline__ void mma_bf16(float c[4], const uint4& a, uint32_t b0, uint32_t b1) {
    asm volatile(
        "mma.sync.aligned.m16n8k16.row.col.f32.bf16.bf16.f32 "
        "{%0,%1,%2,%3}, {%4,%5,%6,%7}, {%8,%9}, {%0,%1,%2,%3};"
        : "+f"(c[0]), "+f"(c[1]), "+f"(c[2]), "+f"(c[3])
        : "r"(a.x), "r"(a.y), "r"(a.z), "r"(a.w), "r"(b0), "r"(b1));
}
__device__ __forceinline__ void ldsm_x4(uint4& d, uint32_t addr) {
    asm volatile("ldmatrix.sync.aligned.m8n8.x4.shared.b16 {%0,%1,%2,%3}, [%4];"
                 : "=r"(d.x), "=r"(d.y), "=r"(d.z), "=r"(d.w) : "r"(addr));
}
__device__ __forceinline__ void ldsm_x4_t(uint4& d, uint32_t addr) {
    asm volatile("ldmatrix.sync.aligned.m8n8.x4.trans.shared.b16 {%0,%1,%2,%3}, [%4];"
                 : "=r"(d.x), "=r"(d.y), "=r"(d.z), "=r"(d.w) : "r"(addr));
}
__device__ __forceinline__ void cp16(uint32_t dst, const void* src, int srcsize) {
    asm volatile("cp.async.cg.shared.global [%0], [%1], 16, %2;\n"
                 :: "r"(dst), "l"(src), "r"(srcsize));
}
__device__ __forceinline__ void cp_commit() {
    asm volatile("cp.async.commit_group;\n");
}
template<int N> __device__ __forceinline__ void cp_wait() {
    asm volatile("cp.async.wait_group %0;\n" :: "n"(N));
}

__device__ __forceinline__ float gelu_f(float x) {
    float x3 = x * x * x;
    return 0.5f * x * (1.f + tanhf(0.7978845608028654f * (x + 0.044715f * x3)));
}

// ---------------- bf16 tensor-core GEMM, 3-stage cp.async (R12 proven) ----------------
#define AST2 20
#define BST2 36
#define STG_A (128*AST2)   // 2560 u32
#define STG_B (32*BST2)    // 1152 u32
#define GEMM_SMEM (3*(STG_A+STG_B)*4)   // 44544 bytes

template<int EPI, int OUTBF>
__device__ __forceinline__ void gemm_body(
        const __nv_bfloat16* __restrict__ A, const __nv_bfloat16* __restrict__ Bm,
        const float* __restrict__ bias, const float* __restrict__ resid,
        void* __restrict__ Cm, int M, int N, int K, int row0, int col0) {
    extern __shared__ uint32_t smu[];
    const uint32_t smem_base = (uint32_t)__cvta_generic_to_shared(smu);

    const int tid  = threadIdx.x;
    const int warp = tid >> 5;
    const int lane = tid & 31;
    const int g    = lane >> 2;
    const int t    = lane & 3;
    const int wr   = warp >> 1;
    const int wc   = warp & 1;

    float acc[2][4][4];
    #pragma unroll
    for (int i = 0; i < 2; i++)
        #pragma unroll
        for (int j = 0; j < 4; j++)
            #pragma unroll
            for (int r = 0; r < 4; r++) acc[i][j][r] = 0.f;

    const int a_r = tid >> 2, a_c = tid & 3;
    const int b_r = tid >> 3, b_c = tid & 7;

#define LOADS(s_) do {                                                              \
        const int k0_ = (s_) * 32;                                                  \
        uint32_t* Ab_ = smu + ((s_) % 3) * (STG_A + STG_B);                         \
        uint32_t* Bb_ = Ab_ + STG_A;                                                \
        _Pragma("unroll")                                                           \
        for (int i_ = 0; i_ < 2; i_++) {                                            \
            int r_ = a_r + i_ * 64;                                                 \
            int gr_ = row0 + r_;                                                    \
            int ok_ = (gr_ < M) ? 16 : 0;                                           \
            const __nv_bfloat16* src_ = A + (size_t)(ok_ ? gr_ : 0) * K + k0_ + a_c * 8; \
            cp16((uint32_t)__cvta_generic_to_shared(Ab_ + r_ * AST2 + a_c * 4), src_, ok_); \
        }                                                                           \
        {                                                                           \
            const __nv_bfloat16* src_ = Bm + (size_t)(k0_ + b_r) * N + col0 + b_c * 8;   \
            cp16((uint32_t)__cvta_generic_to_shared(Bb_ + b_r * BST2 + b_c * 4), src_, 16); \
        }                                                                           \
    } while (0)

    const int steps = K >> 5;
    LOADS(0); cp_commit();
    LOADS(1); cp_commit();

    const int a_lane_off = (lane & 15) * AST2 + (lane >> 4) * 4;
    const int b_lane_off = (lane & 15) * BST2 + wc * 16 + (lane >> 4) * 4;

    for (int s = 0; s < steps; s++) {
        cp_wait<1>();
        __syncthreads();
        if (s + 2 < steps) LOADS(s + 2);
        cp_commit();

        const uint32_t bufo = (uint32_t)((s % 3) * (STG_A + STG_B));
        const uint32_t abase = smem_base + (bufo + wr * 32 * AST2 + a_lane_off) * 4;
        const uint32_t bbase = smem_base + (bufo + STG_A + b_lane_off) * 4;

        #pragma unroll
        for (int ch = 0; ch < 2; ch++) {
            uint4 af[2];
            #pragma unroll
            for (int i = 0; i < 2; i++)
                ldsm_x4(af[i], abase + (i * 16 * AST2 + ch * 8) * 4);
            uint4 bq[2];
            #pragma unroll
            for (int jj = 0; jj < 2; jj++)
                ldsm_x4_t(bq[jj], bbase + (ch * 16 * BST2 + jj * 8) * 4);
            #pragma unroll
            for (int i = 0; i < 2; i++) {
                mma_bf16(acc[i][0], af[i], bq[0].x, bq[0].y);
                mma_bf16(acc[i][1], af[i], bq[0].z, bq[0].w);
                mma_bf16(acc[i][2], af[i], bq[1].x, bq[1].y);
                mma_bf16(acc[i][3], af[i], bq[1].z, bq[1].w);
            }
        }
    }
#undef LOADS

    __syncthreads();

    #pragma unroll
    for (int i = 0; i < 2; i++) {
        int rbase = row0 + wr * 32 + i * 16 + g;
        #pragma unroll
        for (int j = 0; j < 4; j++) {
            int col = col0 + wc * 32 + j * 8 + t * 2;
            float bx = 0.f, by = 0.f;
            if (bias) { bx = bias[col]; by = bias[col + 1]; }
            #pragma unroll
            for (int hh = 0; hh < 2; hh++) {
                int row = rbase + hh * 8;
                if (row < M) {
                    float c0 = acc[i][j][hh * 2 + 0] + bx;
                    float c1 = acc[i][j][hh * 2 + 1] + by;
                    if (EPI == 1) { c0 = gelu_f(c0); c1 = gelu_f(c1); }
                    if (EPI == 2) {
                        float2 rv = *(const float2*)(resid + (size_t)row * N + col);
                        c0 += rv.x; c1 += rv.y;
                    }
                    if (OUTBF) {
                        __nv_bfloat162 p;
                        p.x = __float2bfloat16(c0);
                        p.y = __float2bfloat16(c1);
                        *(__nv_bfloat162*)((__nv_bfloat16*)Cm + (size_t)row * N + col) = p;
                    } else {
                        *(float2*)((float*)Cm + (size_t)row * N + col) = make_float2(c0, c1);
                    }
                }
            }
        }
    }
}

template<int EPI, int OUTBF>
__global__ void __launch_bounds__(256)
tgemm_kernel(const __nv_bfloat16* __restrict__ A, const __nv_bfloat16* __restrict__ Bm,
             const float* __restrict__ bias, const float* __restrict__ resid,
             void* __restrict__ Cm, int M, int N, int K) {
    gemm_body<EPI, OUTBF>(A, Bm, bias, resid, Cm, M, N, K,
                          blockIdx.y * 128, blockIdx.x * 64);
}

// fused QKV + Wp: blockIdx.x in [0,48). [0,36): sel=x/12 picks {q,k,v};
// [36,48): the tiny pe@Wp GEMM (M=101) on blockIdx.y==0 only.
__global__ void __launch_bounds__(256)
qkv_kernel(const __nv_bfloat16* __restrict__ A,
           const __nv_bfloat16* __restrict__ Bq, const __nv_bfloat16* __restrict__ Bk,
           const __nv_bfloat16* __restrict__ Bv, const __nv_bfloat16* __restrict__ Bp,
           const float* __restrict__ bq, const float* __restrict__ bk,
           const float* __restrict__ bv,
           __nv_bfloat16* __restrict__ Cq, __nv_bfloat16* __restrict__ Ck,
           __nv_bfloat16* __restrict__ Cv,
           const __nv_bfloat16* __restrict__ pe, __nv_bfloat16* __restrict__ Cp) {
    int xx = blockIdx.x;
    if (xx < 36) {
        int sel = xx / 12;
        int colblk = xx % 12;
        const __nv_bfloat16* Bm = (sel == 0) ? Bq : (sel == 1) ? Bk : Bv;
        const float* bias       = (sel == 0) ? bq : (sel == 1) ? bk : bv;
        __nv_bfloat16* Cm       = (sel == 0) ? Cq : (sel == 1) ? Ck : Cv;
        gemm_body<0, 1>(A, Bm, bias, nullptr, Cm, BT, CC, CC,
                        blockIdx.y * 128, colblk * 64);
    } else {
        if (blockIdx.y != 0) return;
        int colblk = xx - 36;
        gemm_body<0, 1>(pe, Bp, nullptr, nullptr, Cp, NR, CC, CC,
                        0, colblk * 64);
    }
}

// ---------------- banded rel-pos attention (bf16 tensor-core, TQ=16) ----------------
// R16: combine+mask fused into the warp softmax (reads S1/SC directly, scatters
// bf16 into AT); V staging shares the softmax phase (K dead after phase 2).
// 3 __syncthreads total. smem 56960B -> 4 blocks/SM.
#define TQ 16

#define U_KV 0            // 128 rows x 36 u32 (K, then V)
#define U_QU 4608         // 16 x 36
#define U_QV 5184         // 16 x 36
#define U_PS 5760         // 104 x 36
#define U_S1 9504         // fp32 16 x 124
#define U_SC 11488        // fp32 16 x 104
#define U_AT 13152        // bf16 16 x 68 u32 (= 136 bf16 cols)
#define ATTN_U32 14240
#define ATTN_SMEM_BYTES (ATTN_U32*4)   // 56960

__global__ void __launch_bounds__(256)
attn_kernel(const __nv_bfloat16* __restrict__ q, const __nv_bfloat16* __restrict__ k,
            const __nv_bfloat16* __restrict__ v, const __nv_bfloat16* __restrict__ pc,
            const float* __restrict__ pu, const float* __restrict__ pv,
            __nv_bfloat16* __restrict__ o) {
    extern __shared__ uint32_t su[];
    uint32_t* KV  = su + U_KV;
    uint32_t* QUb = su + U_QU;
    uint32_t* QVb = su + U_QV;
    uint32_t* PSb = su + U_PS;
    float*    S1  = (float*)(su + U_S1);
    float*    SC  = (float*)(su + U_SC);
    uint32_t* AT  = su + U_AT;
    const uint32_t smem_base = (uint32_t)__cvta_generic_to_shared(su);

    const int b  = blockIdx.z;
    const int h  = blockIdx.y;
    const int t0 = blockIdx.x * TQ;
    const int sb = t0 - WHALF;
    const int tid = threadIdx.x;
    const int warp = tid >> 5, lane = tid & 31;
    const int g = lane >> 2, t4 = lane & 3;

    // ---- phase 1: stage QU/QV, K, P ; zero AT
    for (int e = tid; e < TQ * 32; e += 256) {
        int qi = e >> 5, cu = e & 31;
        int tt = t0 + qi;
        float f0 = 0.f, f1 = 0.f;
        if (tt < TT) {
            uint32_t raw = *(const uint32_t*)(q + ((size_t)(b*TT+tt))*CC + h*DKK + cu*2);
            __nv_bfloat162 p = *(__nv_bfloat162*)&raw;
            f0 = __bfloat162float(p.x); f1 = __bfloat162float(p.y);
        }
        float u0 = pu[h*DKK + cu*2], u1 = pu[h*DKK + cu*2 + 1];
        float w0 = pv[h*DKK + cu*2], w1 = pv[h*DKK + cu*2 + 1];
        __nv_bfloat162 a, c;
        a.x = __float2bfloat16(f0 + u0); a.y = __float2bfloat16(f1 + u1);
        c.x = __float2bfloat16(f0 + w0); c.y = __float2bfloat16(f1 + w1);
        QUb[qi*36 + cu] = *(uint32_t*)&a;
        QVb[qi*36 + cu] = *(uint32_t*)&c;
    }
    for (int e = tid; e < 120 * 8; e += 256) {
        int si = e >> 3, c = e & 7;
        int s = sb + si;
        uint4 kk = make_uint4(0,0,0,0);
        if (s >= 0 && s < TT) kk = *(const uint4*)(k + ((size_t)(b*TT+s))*CC + h*DKK + c*8);
        *(uint4*)(KV + si*36 + c*4) = kk;
    }
    for (int e = tid; e < 104 * 8; e += 256) {
        int r = e >> 3, c = e & 7;
        uint4 pp = make_uint4(0,0,0,0);
        if (r < NR) pp = *(const uint4*)(pc + (size_t)r*CC + h*DKK + c*8);
        *(uint4*)(PSb + r*36 + c*4) = pp;
    }
    for (int e = tid; e < TQ * 68; e += 256) AT[e] = 0u;
    __syncthreads();

    // ---- phase 2: score GEMMs (A fragments hoisted)
    {
        uint4 af[4];
        #pragma unroll
        for (int ch = 0; ch < 4; ch++) {
            af[ch].x = QUb[g*36 + ch*8 + t4];
            af[ch].y = QUb[(g+8)*36 + ch*8 + t4];
            af[ch].z = QUb[g*36 + ch*8 + t4 + 4];
            af[ch].w = QUb[(g+8)*36 + ch*8 + t4 + 4];
        }
        for (int nt = warp; nt < 15; nt += 8) {
            float c[4] = {0.f, 0.f, 0.f, 0.f};
            #pragma unroll
            for (int ch = 0; ch < 4; ch++) {
                uint32_t b0 = KV[(nt*8+g)*36 + ch*8 + t4];
                uint32_t b1 = KV[(nt*8+g)*36 + ch*8 + t4 + 4];
                mma_bf16(c, af[ch], b0, b1);
            }
            *(float2*)(S1 + g*124 + nt*8 + 2*t4)     = make_float2(c[0], c[1]);
            *(float2*)(S1 + (g+8)*124 + nt*8 + 2*t4) = make_float2(c[2], c[3]);
        }
        #pragma unroll
        for (int ch = 0; ch < 4; ch++) {
            af[ch].x = QVb[g*36 + ch*8 + t4];
            af[ch].y = QVb[(g+8)*36 + ch*8 + t4];
            af[ch].z = QVb[g*36 + ch*8 + t4 + 4];
            af[ch].w = QVb[(g+8)*36 + ch*8 + t4 + 4];
        }
        for (int nt = warp; nt < 13; nt += 8) {
            float c[4] = {0.f, 0.f, 0.f, 0.f};
            #pragma unroll
            for (int ch = 0; ch < 4; ch++) {
                uint32_t b0 = PSb[(nt*8+g)*36 + ch*8 + t4];
                uint32_t b1 = PSb[(nt*8+g)*36 + ch*8 + t4 + 4];
                mma_bf16(c, af[ch], b0, b1);
            }
            *(float2*)(SC + g*104 + nt*8 + 2*t4)     = make_float2(c[0], c[1]);
            *(float2*)(SC + (g+8)*104 + nt*8 + 2*t4) = make_float2(c[2], c[3]);
        }
    }
    __syncthreads();

    // ---- phase 3: stage V (K dead) ; warp softmax fused with combine+mask+scatter
    for (int e = tid; e < 128 * 8; e += 256) {
        int si = e >> 3, c = e & 7;
        int s = sb + si;
        uint4 vv = make_uint4(0,0,0,0);
        if (si < 120 && s >= 0 && s < TT)
            vv = *(const uint4*)(v + ((size_t)(b*TT+s))*CC + h*DKK + c*8);
        *(uint4*)(KV + si*36 + c*4) = vv;
    }
    {
        #pragma unroll
        for (int rr = 0; rr < 2; rr++) {
            int qi = warp * 2 + rr;
            int tt = t0 + qi;
            const float* s1row = S1 + qi * 124 + qi;
            const float* scrow = SC + qi * 104;
            // lane holds scores r = lane, +32, +64, +96 (combine+mask in regs)
            float vr[4];
            #pragma unroll
            for (int cc4 = 0; cc4 < 4; cc4++) {
                int r = lane + cc4 * 32;
                int s = tt + r - WHALF;
                bool ok = (r < NR) && (tt < TT) && (s >= 0) && (s < TT);
                vr[cc4] = ok ? (s1row[r] + scrow[r]) * 0.125f : -1e30f;
            }
            float m = fmaxf(fmaxf(vr[0], vr[1]), fmaxf(vr[2], vr[3]));
            #pragma unroll
            for (int oo = 16; oo; oo >>= 1)
                m = fmaxf(m, __shfl_xor_sync(0xffffffffu, m, oo));
            float e0 = __expf(vr[0] - m);
            float e1 = __expf(vr[1] - m);
            float e2 = __expf(vr[2] - m);
            float e3 = (lane + 96 < NR) ? __expf(vr[3] - m) : 0.f;
            float sum = e0 + e1 + e2 + e3;
            #pragma unroll
            for (int oo = 16; oo; oo >>= 1)
                sum += __shfl_xor_sync(0xffffffffu, sum, oo);
            float inv = 1.f / sum;
            __nv_bfloat16* at = (__nv_bfloat16*)AT + qi * 136 + qi;
            at[lane]      = __float2bfloat16(e0 * inv);
            at[lane + 32] = __float2bfloat16(e1 * inv);
            at[lane + 64] = __float2bfloat16(e2 * inv);
            if (lane + 96 < NR) at[lane + 96] = __float2bfloat16(e3 * inv);
        }
    }
    __syncthreads();

    // ---- phase 4: O = AT(16x128) @ V(128x64); warps 0-3, n16 each
    if (warp < 4) {
        int n0 = warp * 16;
        float c0[4] = {0.f,0.f,0.f,0.f};
        float c1[4] = {0.f,0.f,0.f,0.f};
        uint32_t vbase = smem_base + (U_KV + (lane & 15)*36 + (n0 >> 1) + (lane >> 4)*4) * 4;
        #pragma unroll
        for (int ch = 0; ch < 8; ch++) {
            uint4 a;
            a.x = AT[g*68 + ch*8 + t4];
            a.y = AT[(g+8)*68 + ch*8 + t4];
            a.z = AT[g*68 + ch*8 + t4 + 4];
            a.w = AT[(g+8)*68 + ch*8 + t4 + 4];
            uint4 bq;
            ldsm_x4_t(bq, vbase + (ch * 16 * 36) * 4);
            mma_bf16(c0, a, bq.x, bq.y);
            mma_bf16(c1, a, bq.z, bq.w);
        }
        int tg0 = t0 + g, tg1 = t0 + g + 8;
        if (tg0 < TT) {
            __nv_bfloat16* orow = o + ((size_t)(b*TT+tg0))*CC + h*DKK;
            __nv_bfloat162 p;
            p.x = __float2bfloat16(c0[0]); p.y = __float2bfloat16(c0[1]);
            *(__nv_bfloat162*)(orow + n0 + 2*t4) = p;
            p.x = __float2bfloat16(c1[0]); p.y = __float2bfloat16(c1[1]);
            *(__nv_bfloat162*)(orow + n0 + 8 + 2*t4) = p;
        }
        if (tg1 < TT) {
            __nv_bfloat16* orow = o + ((size_t)(b*TT+tg1))*CC + h*DKK;
            __nv_bfloat162 p;
            p.x = __float2bfloat16(c0[2]); p.y = __float2bfloat16(c0[3]);
            *(__nv_bfloat162*)(orow + n0 + 2*t4) = p;
            p.x = __float2bfloat16(c1[2]); p.y = __float2bfloat16(c1[3]);
            *(__nv_bfloat162*)(orow + n0 + 8 + 2*t4) = p;
        }
    }
}

// ---------------- driver ----------------
extern "C" void kernel_launch(void* const* d_in, const int* in_sizes, int n_in,
                              void* d_out, int out_size) {
    const float* x    = (const float*)d_in[0];
    const float* Wq   = (const float*)d_in[1];
    const float* bq   = (const float*)d_in[2];
    const float* Wk   = (const float*)d_in[3];
    const float* bk   = (const float*)d_in[4];
    const float* Wv   = (const float*)d_in[5];
    const float* bv   = (const float*)d_in[6];
    const float* Wo   = (const float*)d_in[7];
    const float* bo   = (const float*)d_in[8];
    const float* Wp   = (const float*)d_in[9];
    const float* pu   = (const float*)d_in[10];
    const float* pvv  = (const float*)d_in[11];
    const float* ln1g = (const float*)d_in[12];
    const float* ln1b = (const float*)d_in[13];
    const float* ln2g = (const float*)d_in[14];
    const float* ln2b = (const float*)d_in[15];
    const float* W1   = (const float*)d_in[16];
    const float* b1   = (const float*)d_in[17];
    const float* W2   = (const float*)d_in[18];
    const float* b2   = (const float*)d_in[19];
    // d_in[20] = att_mask: fixed band |i-j|>50, handled analytically.

    float* h;
    __nv_bfloat16 *ybf, *obf, *qb, *kb, *vb, *pcb, *pebf, *wbf;
    cudaGetSymbolAddress((void**)&h,    g_h);
    cudaGetSymbolAddress((void**)&ybf,  g_ybf);
    cudaGetSymbolAddress((void**)&obf,  g_obf);
    cudaGetSymbolAddress((void**)&qb,   g_qb);
    cudaGetSymbolAddress((void**)&kb,   g_kb);
    cudaGetSymbolAddress((void**)&vb,   g_vb);
    cudaGetSymbolAddress((void**)&pcb,  g_pcb);
    cudaGetSymbolAddress((void**)&pebf, g_pebf);
    cudaGetSymbolAddress((void**)&wbf,  g_wbf);

    cudaFuncSetAttribute(tgemm_kernel<1,1>, cudaFuncAttributeMaxDynamicSharedMemorySize, GEMM_SMEM);
    cudaFuncSetAttribute(tgemm_kernel<2,0>, cudaFuncAttributeMaxDynamicSharedMemorySize, GEMM_SMEM);
    cudaFuncSetAttribute(qkv_kernel,        cudaFuncAttributeMaxDynamicSharedMemorySize, GEMM_SMEM);
    cudaFuncSetAttribute(attn_kernel,       cudaFuncAttributeMaxDynamicSharedMemorySize, ATTN_SMEM_BYTES);

    setup_kernel<<<SETUP_BLKS, 256>>>(x, Wq, Wk, Wv, Wo, Wp, W1, W2);

    dim3 gBig(CC / 64, (BT + 127) / 128);        // (12, 32)
    dim3 gQKV(48, (BT + 127) / 128);             // (48, 32): qkv + fused Wp
    dim3 gAtt((TT + TQ - 1) / TQ, HH, BB);       // (63, 12, 4)

    for (int l = 0; l < LNUM; l++) {
        size_t wOff = (size_t)l * CC * CC;
        size_t bOff = (size_t)l * CC;

        ln_kernel<<<BT, 192>>>(h, ybf, ln1g + bOff, ln1b + bOff);
        qkv_kernel<<<gQKV, 256, GEMM_SMEM>>>(ybf,
            wbf + 0*WSZ + wOff, wbf + 1*WSZ + wOff, wbf + 2*WSZ + wOff,
            wbf + 4*WSZ + wOff,
            bq + bOff, bk + bOff, bv + bOff, qb, kb, vb, pebf, pcb);
        attn_kernel<<<gAtt, 256, ATTN_SMEM_BYTES>>>(qb, kb, vb, pcb, pu + bOff, pvv + bOff, obf);
        tgemm_kernel<2,0><<<gBig, 256, GEMM_SMEM>>>(obf, wbf + 3*WSZ + wOff,
            bo + bOff, h, h, BT, CC, CC);
        ln_kernel<<<BT, 192>>>(h, ybf, ln2g + bOff, ln2b + bOff);
        tgemm_kernel<1,1><<<gBig, 256, GEMM_SMEM>>>(ybf, wbf + 5*WSZ + wOff,
            b1 + bOff, nullptr, obf, BT, CC, CC);
        void* outp = (l == LNUM - 1) ? d_out : (void*)h;
        tgemm_kernel<2,0><<<gBig, 256, GEMM_SMEM>>>(obf, wbf + 6*WSZ + wOff,
            b2 + bOff, h, outp, BT, CC, CC);
    }
}